// round 14
// baseline (speedup 1.0000x reference)
#include <cuda_runtime.h>
#include <cuda_bf16.h>
#include <cstdint>

#define Bb   8
#define Pp   8192
#define CIN  64
#define KK   32
#define Mm   2048
#define NROWS (Bb*Mm*KK)     // 524288
#define BN_EPS 1e-5f

// ---------------- scratch (device globals; no allocation) ----------------
__device__ __align__(128) __nv_bfloat16 g_fh[(size_t)Bb*Pp*CIN]; // feats hi (8 MB)
__device__ __align__(128) __nv_bfloat16 g_fl[(size_t)Bb*Pp*CIN]; // feats lo (8 MB)
__device__ __align__(128) float4 g_xyz4[(size_t)Bb*Pp];          // (x,y,z,|x|^2)
__device__ __align__(128) int    g_sel[(size_t)NROWS];           // 2 MB
__device__ __align__(128) float  g_y1[(size_t)NROWS*64];         // 134 MB
__device__ __align__(128) float  g_y2[(size_t)NROWS*64];         // 134 MB
__device__ __align__(128) float  g_maxf[(size_t)Bb*128*Mm];      // 8 MB
// weight hi/lo bf16 images (unswizzled, K-major rows)
__device__ __align__(128) __nv_bfloat16 g_Wh0[64*80],  g_Wl0[64*80];
__device__ __align__(128) __nv_bfloat16 g_Wh1[64*64],  g_Wl1[64*64];
__device__ __align__(128) __nv_bfloat16 g_Wh2[128*64], g_Wl2[128*64];
__device__ double g_sum[3][128];
__device__ double g_sq[3][128];
__device__ float  g_s[3][128];
__device__ float  g_t[3][128];

// ---------------- small helpers ------------------------------------------
__device__ __forceinline__ uint32_t smem_u32(const void* p) {
    uint32_t a;
    asm("{ .reg .u64 t; cvta.to.shared.u64 t, %1; cvt.u32.u64 %0, t; }" : "=r"(a) : "l"(p));
    return a;
}
__device__ __forceinline__ unsigned pkb(__nv_bfloat16 a, __nv_bfloat16 b) {
    __nv_bfloat162 t; t.x = a; t.y = b;
    return *(unsigned*)&t;
}
__device__ __forceinline__ void wsplit(float w, __nv_bfloat16& h, __nv_bfloat16& l) {
    h = __float2bfloat16(w);
    l = __float2bfloat16(w - __bfloat162float(h));
}
__device__ __forceinline__ unsigned cvt2bf(float hi, float lo) {
    unsigned r;
    asm("cvt.rn.bf16x2.f32 %0, %1, %2;" : "=r"(r) : "f"(hi), "f"(lo));
    return r;
}
__device__ __forceinline__ void ldsm4(unsigned* r, uint32_t addr) {
    asm volatile("ldmatrix.sync.aligned.m8n8.x4.shared.b16 {%0,%1,%2,%3}, [%4];"
        : "=r"(r[0]), "=r"(r[1]), "=r"(r[2]), "=r"(r[3]) : "r"(addr));
}
__device__ __forceinline__ void mma16816(float* c, const unsigned* a,
                                         unsigned b0, unsigned b1) {
    asm volatile("mma.sync.aligned.m16n8k16.row.col.f32.bf16.bf16.f32 "
        "{%0,%1,%2,%3}, {%4,%5,%6,%7}, {%8,%9}, {%0,%1,%2,%3};"
        : "+f"(c[0]), "+f"(c[1]), "+f"(c[2]), "+f"(c[3])
        : "r"(a[0]), "r"(a[1]), "r"(a[2]), "r"(a[3]), "r"(b0), "r"(b1));
}
__device__ __forceinline__ unsigned mapu(float d) {
    unsigned u = __float_as_uint(d);
    return u ^ ((unsigned)(((int)u) >> 31) | 0x80000000u);
}
// packed f32x2 (exact per-lane fp32 rn)
#define PACK2(d, lo, hi)    asm("mov.b64 %0, {%1,%2};" : "=l"(d) : "f"(lo), "f"(hi))
#define UNPACK2F(lo, hi, v) asm("mov.b64 {%0,%1}, %2;" : "=f"(lo), "=f"(hi) : "l"(v))
#define MUL2(d, a, b)       asm("mul.rn.f32x2 %0, %1, %2;" : "=l"(d) : "l"(a), "l"(b))
#define ADD2(d, a, b)       asm("add.rn.f32x2 %0, %1, %2;" : "=l"(d) : "l"(a), "l"(b))
#define FMA2(d, a, b, c)    asm("fma.rn.f32x2 %0, %1, %2, %3;" : "=l"(d) : "l"(a), "l"(b), "l"(c))

// ---------------- prep: zero stats + bf16 hi/lo weight images -------------
__global__ void prep_kernel(const float* __restrict__ W1,
                            const float* __restrict__ W2,
                            const float* __restrict__ W3)
{
    int tid = blockIdx.x * blockDim.x + threadIdx.x;
    if (tid < 384) { ((double*)g_sum)[tid] = 0.0; ((double*)g_sq)[tid] = 0.0; }
    if (tid >= 5120 + 4096 + 8192) return;
    float w;
    __nv_bfloat16 *ph, *pl;
    int idx;
    if (tid < 5120) {                   // W0: [64][80] = feats(64)+xyz(3)+pad
        int n = tid / 80, k = tid % 80;
        if (k < 64)      w = W1[n*67 + k + 3];
        else if (k < 67) w = W1[n*67 + (k - 64)];
        else             w = 0.f;
        ph = g_Wh0; pl = g_Wl0; idx = tid;
    } else if (tid < 9216) {            // W1: [64][64]
        int t = tid - 5120;
        w = W2[t];
        ph = g_Wh1; pl = g_Wl1; idx = t;
    } else {                            // W2: [128][64]
        int t = tid - 9216;
        w = W3[t];
        ph = g_Wh2; pl = g_Wl2; idx = t;
    }
    __nv_bfloat16 h, l; wsplit(w, h, l);
    ph[idx] = h; pl[idx] = l;
}

// ---------------- xyz -> float4 (x,y,z,|x|^2) -----------------------------
__global__ void pad_kernel(const float* __restrict__ xyz)
{
    int i = blockIdx.x * blockDim.x + threadIdx.x;   // Bb*Pp
    const float* s = xyz + (size_t)i*3;
    float x = s[0], y = s[1], z = s[2];
    float n = __fadd_rn(__fadd_rn(__fmul_rn(x,x), __fmul_rn(y,y)), __fmul_rn(z,z));
    g_xyz4[i] = make_float4(x, y, z, n);
}

// ---------------- feats (B,C,P) -> bf16 hi/lo (B,P,C) ---------------------
__global__ void transpose_kernel(const float* __restrict__ f)
{
    __shared__ float tile[32][33];
    int b  = blockIdx.z;
    int c0 = blockIdx.y * 32;
    int p0 = blockIdx.x * 32;
    int tx = threadIdx.x, ty = threadIdx.y;
    #pragma unroll
    for (int i = ty; i < 32; i += 8)
        tile[i][tx] = f[((size_t)b*CIN + c0 + i)*Pp + p0 + tx];
    __syncthreads();
    #pragma unroll
    for (int i = ty; i < 32; i += 8) {
        float v = tile[tx][i];
        __nv_bfloat16 h, l; wsplit(v, h, l);
        size_t o = ((size_t)b*Pp + p0 + i)*CIN + c0 + tx;
        g_fh[o] = h;
        g_fl[o] = l;
    }
}

// --- KNN: 4 q/block, 2-pass sample pivot, FAST-filter sweep, exact tail ---
#define CAPQ 1280
__global__ void __launch_bounds__(256, 4) knn_kernel(float* __restrict__ centers_out)
{
    int blk = blockIdx.x;          // 0..4095
    int b   = blk >> 9;
    int mbase = (blk & 511) * 4;

    extern __shared__ char sm[];
    unsigned* hist    = (unsigned*)sm;                 // 1024 bins (4 x 256)
    unsigned* cand_dm = hist + 1024;                   // 4*CAPQ
    int*      cand_id = (int*)(cand_dm + 4*CAPQ);      // 4*CAPQ
    __shared__ float    ctr[4][4];
    __shared__ float    sTf[4];
    __shared__ unsigned s_prefix[4];
    __shared__ int s_remaining[4], s_ncand[4], s_cnt[4];
    __shared__ int s_min4[4], s_last4[4];
    __shared__ int s_maxrem;

    int tid  = threadIdx.x;
    int wid  = tid >> 5;
    int lane = tid & 31;
    const float4* X4 = g_xyz4 + ((size_t)b << 13);

    if (tid < 4) {
        int m = mbase + tid;
        int ci = (m == 2047) ? 8191
               : (int)(__fmul_rn(8191.0f, __fdiv_rn((float)m, 2047.0f)));
        float4 cp = X4[ci];
        ctr[tid][0] = cp.x; ctr[tid][1] = cp.y; ctr[tid][2] = cp.z; ctr[tid][3] = cp.w;
        float* co = centers_out + (size_t)(b*2048 + m)*3;
        co[0] = cp.x; co[1] = cp.y; co[2] = cp.z;
        s_prefix[tid] = 0u; s_remaining[tid] = KK;
        s_ncand[tid] = 0; s_cnt[tid] = 0; s_last4[tid] = -1;
    }
    __syncthreads();
    float cxq[4], cyq[4], czq[4], cnq[4];
    #pragma unroll
    for (int q = 0; q < 4; q++) {
        cxq[q] = ctr[q][0]; cyq[q] = ctr[q][1]; czq[q] = ctr[q][2]; cnq[q] = ctr[q][3];
    }
    // exact reference rounding chain (sample, appends, fallback)
    auto distq = [&](int q, float4 X) -> float {
        float dt = __fadd_rn(__fadd_rn(__fmul_rn(cxq[q],X.x), __fmul_rn(cyq[q],X.y)),
                             __fmul_rn(czq[q],X.z));
        return __fsub_rn(__fadd_rn(cnq[q], X.w), __fmul_rn(2.0f, dt));
    };
    auto hadd = [&](bool ok, unsigned bkt) {
        unsigned mask = __ballot_sync(0xffffffffu, ok);
        if (ok) {
            unsigned peers = __match_any_sync(mask, bkt);
            if ((peers & ((1u << lane) - 1u)) == 0u)
                atomicAdd(&hist[bkt], __popc(peers));
        }
    };
    auto scanq = [&](int q, int base) {
        unsigned cum[8];
        unsigned run = 0;
        #pragma unroll
        for (int i = 0; i < 8; i++) { run += hist[base + lane*8 + i]; cum[i] = run; }
        unsigned tot = run;
        unsigned off = tot;
        #pragma unroll
        for (int dd = 1; dd < 32; dd <<= 1) {
            unsigned v = __shfl_up_sync(0xffffffffu, off, dd);
            if (lane >= dd) off += v;
        }
        off -= tot;
        unsigned rem = (unsigned)s_remaining[q];
        #pragma unroll
        for (int i = 0; i < 8; i++) {
            unsigned prev = off + (i ? cum[i-1] : 0u);
            unsigned cu   = off + cum[i];
            if (prev < rem && cu >= rem) {
                s_prefix[q] = (s_prefix[q] << 8) | (unsigned)(lane*8 + i);
                s_remaining[q] = (int)(rem - prev);
            }
        }
    };

    // ---- sample phase: 512 points {16t,16t+1}; 2 passes (16-bit pivot) ----
    unsigned sd[4][2];
    {
        float4 A = __ldg(X4 + 16*tid);
        float4 Bp = __ldg(X4 + 16*tid + 1);
        #pragma unroll
        for (int q = 0; q < 4; q++) {
            sd[q][0] = mapu(distq(q, A));
            sd[q][1] = mapu(distq(q, Bp));
        }
    }
    for (int pass = 0; pass < 2; pass++) {
        #pragma unroll
        for (int t = tid; t < 1024; t += 256) hist[t] = 0;
        __syncthreads();
        unsigned prefq[4];
        #pragma unroll
        for (int q = 0; q < 4; q++) prefq[q] = s_prefix[q];
        int sh = 24 - 8*pass;
        #pragma unroll
        for (int q = 0; q < 4; q++) {
            #pragma unroll
            for (int k = 0; k < 2; k++) {
                bool ok = (pass == 0) || ((sd[q][k] >> (sh + 8)) == prefq[q]);
                hadd(ok, (unsigned)(q*256) + ((sd[q][k] >> sh) & 255u));
            }
        }
        __syncthreads();
        if (wid < 4) scanq(wid, wid*256);
        __syncthreads();
    }
    if (tid < 4) {
        // pivot = TOP of the 16-bit bucket holding the sample kth (upper bound)
        unsigned mv = (s_prefix[tid] << 16) | 0xFFFFu;
        unsigned u  = (mv & 0x80000000u) ? (mv ^ 0x80000000u) : ~mv;
        sTf[tid] = __uint_as_float(u);
        s_prefix[tid] = 0u; s_remaining[tid] = KK;
    }
    __syncthreads();
    float Tf[4] = {sTf[0], sTf[1], sTf[2], sTf[3]};

    // packed query constants: {q0,q1} and {q2,q3}
    unsigned long long qx01, qx23, qy01, qy23, qz01, qz23, qn01, qn23;
    PACK2(qx01, cxq[0], cxq[1]); PACK2(qx23, cxq[2], cxq[3]);
    PACK2(qy01, cyq[0], cyq[1]); PACK2(qy23, cyq[2], cyq[3]);
    PACK2(qz01, czq[0], czq[1]); PACK2(qz23, czq[2], czq[3]);
    PACK2(qn01, cnq[0], cnq[1]); PACK2(qn23, cnq[2], cnq[3]);
    unsigned long long neg2p, negep;
    {
        float n2 = -2.0f, ne = -2e-6f;
        PACK2(neg2p, n2, n2); PACK2(negep, ne, ne);
    }

    // ---- main sweep: fast FMA filter with certified margin ----
    // d_fast = fma(-2, fma(cx,x,fma(cy,y,cz*z)), s) - 2e-6*s, s = cn+|x|^2.
    // |d_fast - d_exact| <= 8*eps*s < 2e-6*s, so d_exact <= Tf => d_cmp <= Tf.
    // Appends recompute the EXACT chain, keeping selection bit-identical.
    #pragma unroll 4
    for (int jj = 0; jj < 32; jj++) {
        int p = tid + jj*256;
        float4 X = __ldg(X4 + p);
        unsigned long long Xx, Xy, Xz, Xw;
        PACK2(Xx, X.x, X.x); PACK2(Xy, X.y, X.y);
        PACK2(Xz, X.z, X.z); PACK2(Xw, X.w, X.w);
        unsigned long long t, s, d01, d23;
        MUL2(t, qz01, Xz);
        FMA2(t, qy01, Xy, t);
        FMA2(t, qx01, Xx, t);
        ADD2(s, qn01, Xw);
        FMA2(d01, neg2p, t, s);
        FMA2(d01, negep, s, d01);
        MUL2(t, qz23, Xz);
        FMA2(t, qy23, Xy, t);
        FMA2(t, qx23, Xx, t);
        ADD2(s, qn23, Xw);
        FMA2(d23, neg2p, t, s);
        FMA2(d23, negep, s, d23);
        float d0, d1, d2, d3;
        UNPACK2F(d0, d1, d01);
        UNPACK2F(d2, d3, d23);
        if (d0 <= Tf[0]) {
            int pos = atomicAdd(&s_ncand[0], 1);
            if (pos < CAPQ) { cand_dm[0*CAPQ + pos] = mapu(distq(0, X)); cand_id[0*CAPQ + pos] = p; }
        }
        if (d1 <= Tf[1]) {
            int pos = atomicAdd(&s_ncand[1], 1);
            if (pos < CAPQ) { cand_dm[1*CAPQ + pos] = mapu(distq(1, X)); cand_id[1*CAPQ + pos] = p; }
        }
        if (d2 <= Tf[2]) {
            int pos = atomicAdd(&s_ncand[2], 1);
            if (pos < CAPQ) { cand_dm[2*CAPQ + pos] = mapu(distq(2, X)); cand_id[2*CAPQ + pos] = p; }
        }
        if (d3 <= Tf[3]) {
            int pos = atomicAdd(&s_ncand[3], 1);
            if (pos < CAPQ) { cand_dm[3*CAPQ + pos] = mapu(distq(3, X)); cand_id[3*CAPQ + pos] = p; }
        }
    }
    __syncthreads();

    int nc[4];
    bool anyofl = false;
    #pragma unroll
    for (int q = 0; q < 4; q++) { nc[q] = s_ncand[q]; anyofl |= (nc[q] > CAPQ); }

    // ---- candidate radix: 4 queries in PARALLEL (exact cand_dm stored) ----
    for (int pass = 0; pass < 4; pass++) {
        #pragma unroll
        for (int t = tid; t < 1024; t += 256) hist[t] = 0;
        __syncthreads();
        int sh = 24 - 8*pass;
        #pragma unroll
        for (int q = 0; q < 4; q++) {
            if (nc[q] > CAPQ) continue;
            unsigned pref = s_prefix[q];
            for (int it = 0; it*256 < nc[q]; it++) {
                int t = it*256 + tid;
                unsigned dv = (t < nc[q]) ? cand_dm[q*CAPQ + t] : 0u;
                bool ok = (t < nc[q]) && ((pass == 0) || ((dv >> (sh + 8)) == pref));
                hadd(ok, (unsigned)(q*256) + ((dv >> sh) & 255u));
            }
        }
        __syncthreads();
        if (wid < 4 && nc[wid] <= CAPQ) scanq(wid, wid*256);
        __syncthreads();
    }

    // ---- selection: 4 queries in parallel ----
    #pragma unroll
    for (int q = 0; q < 4; q++) {
        if (nc[q] > CAPQ) continue;
        unsigned thr = s_prefix[q];
        int* selg = g_sel + (size_t)(b*2048 + mbase + q) * KK;
        for (int it = 0; it*256 < nc[q]; it++) {
            int t = it*256 + tid;
            if (t < nc[q] && cand_dm[q*CAPQ + t] < thr) {
                int s = atomicAdd(&s_cnt[q], 1);
                selg[s] = cand_id[q*CAPQ + t];
            }
        }
    }
    __syncthreads();
    if (tid == 0) {
        int mr = 0;
        for (int q = 0; q < 4; q++)
            if (nc[q] <= CAPQ && s_remaining[q] > mr) mr = s_remaining[q];
        s_maxrem = mr;
    }
    __syncthreads();
    int maxrem = s_maxrem;
    for (int r = 0; r < maxrem; r++) {
        if (tid < 4) s_min4[tid] = 0x7fffffff;
        __syncthreads();
        #pragma unroll
        for (int q = 0; q < 4; q++) {
            if (nc[q] > CAPQ || r >= s_remaining[q]) continue;
            unsigned thr = s_prefix[q];
            int last = s_last4[q];
            for (int it = 0; it*256 < nc[q]; it++) {
                int t = it*256 + tid;
                if (t < nc[q] && cand_dm[q*CAPQ + t] == thr && cand_id[q*CAPQ + t] > last)
                    atomicMin(&s_min4[q], cand_id[q*CAPQ + t]);
            }
        }
        __syncthreads();
        if (tid < 4) {
            int q = tid;
            if (nc[q] <= CAPQ && r < s_remaining[q]) {
                int* selg = g_sel + (size_t)(b*2048 + mbase + q) * KK;
                selg[s_cnt[q] + r] = s_min4[q];
                s_last4[q] = s_min4[q];
            }
        }
        __syncthreads();
    }

    // ---- exact fallback for overflow queries (rare) ----
    if (anyofl) {
        for (int q = 0; q < 4; q++) {
            if (nc[q] <= CAPQ) continue;
            __syncthreads();
            if (tid == 0) { s_prefix[q] = 0u; s_remaining[q] = KK; s_cnt[q] = 0; s_last4[q] = -1; }
            __syncthreads();
            for (int pass = 0; pass < 4; pass++) {
                hist[tid] = 0;
                __syncthreads();
                unsigned pref = s_prefix[q];
                int sh = 24 - 8*pass;
                for (int jj = 0; jj < 32; jj++) {
                    float4 X = __ldg(X4 + tid + jj*256);
                    unsigned u = mapu(distq(q, X));
                    bool ok = (pass == 0) || ((u >> (sh + 8)) == pref);
                    hadd(ok, (u >> sh) & 255u);
                }
                __syncthreads();
                if (wid == 0) scanq(q, 0);
                __syncthreads();
            }
            unsigned thr = s_prefix[q];
            int rem = s_remaining[q];
            int* selg = g_sel + (size_t)(b*2048 + mbase + q) * KK;
            for (int jj = 0; jj < 32; jj++) {
                int p = tid + jj*256;
                float4 X = __ldg(X4 + p);
                if (mapu(distq(q, X)) < thr) {
                    int s = atomicAdd(&s_cnt[q], 1);
                    selg[s] = p;
                }
            }
            __syncthreads();
            int base = s_cnt[q];
            for (int r = 0; r < rem; r++) {
                if (tid == 0) s_min4[0] = 0x7fffffff;
                __syncthreads();
                int last = s_last4[q];
                for (int jj = 0; jj < 32; jj++) {
                    int p = tid + jj*256;
                    float4 X = __ldg(X4 + p);
                    if (mapu(distq(q, X)) == thr && p > last) atomicMin(&s_min4[0], p);
                }
                __syncthreads();
                if (tid == 0) { selg[base + r] = s_min4[0]; s_last4[q] = s_min4[0]; }
                __syncthreads();
            }
        }
    }
}

// ---------------- bf16x3 GEMM via mma.sync (HMMA tensor pipe) -------------
template<int LAYER>
__global__ void __launch_bounds__(256) mma_kernel(const float* __restrict__ bias,
                                                  const float* __restrict__ centers)
{
    constexpr int CO    = (LAYER == 2) ? 128 : 64;
    constexpr int K     = (LAYER == 0) ? 80 : 64;
    constexpr int KC    = K / 8;
    constexpr int NKCH  = K / 16;
    constexpr int ST    = (LAYER == 0) ? 24 : 16;
    constexpr int ASZ   = 128 * ST * 16;
    constexpr int WCOLS = CO / 2;
    constexpr int NT    = WCOLS / 8;
    constexpr int HC    = KC / 2;

    extern __shared__ __align__(16) char dyn[];
    char* Asm = dyn;
    char* Bsm = dyn + ASZ;
    __shared__ float sb[CO], ssum[CO], ssq[CO];
    __shared__ float sS[64], sT[64];

    const int tid = threadIdx.x;
    const size_t rowBase = (size_t)blockIdx.x * 128;
    const int bBat = (int)(rowBase >> 16);

    if (tid < CO) { sb[tid] = bias[tid]; ssum[tid] = 0.f; ssq[tid] = 0.f; }
    if (LAYER > 0 && tid < 64) { sS[tid] = g_s[LAYER-1][tid]; sT[tid] = g_t[LAYER-1][tid]; }
    __syncthreads();

    // ---- A build: 2 threads per row ----
    {
        int row = tid >> 1, half = tid & 1;
        int rx = row & 7;
        unsigned rowOff = (unsigned)row * (ST*16);
        if (LAYER == 0) {
            int p = g_sel[rowBase + row];
            const uint4* FH = (const uint4*)g_fh + (((size_t)bBat << 13) + (unsigned)p) * 8;
            const uint4* FL = (const uint4*)g_fl + (((size_t)bBat << 13) + (unsigned)p) * 8;
            #pragma unroll
            for (int j = 0; j < HC; j++) {
                int c = half*HC + j;
                uint4 hv4, lv4;
                if (c < 8) {
                    hv4 = __ldg(FH + c);
                    lv4 = __ldg(FL + c);
                } else if (c == 8) {
                    float4 X = g_xyz4[((size_t)bBat << 13) + (unsigned)p];
                    int bm = (int)((rowBase + row) >> 5);
                    float dx = X.x - centers[bm*3 + 0];
                    float dy = X.y - centers[bm*3 + 1];
                    float dz = X.z - centers[bm*3 + 2];
                    unsigned h01 = cvt2bf(dy, dx);
                    float h0f = __uint_as_float(h01 << 16);
                    float h1f = __uint_as_float(h01 & 0xffff0000u);
                    unsigned l01 = cvt2bf(dy - h1f, dx - h0f);
                    unsigned h2 = cvt2bf(0.f, dz);
                    float h2f = __uint_as_float(h2 << 16);
                    unsigned l2 = cvt2bf(0.f, dz - h2f);
                    hv4 = make_uint4(h01, h2, 0u, 0u);
                    lv4 = make_uint4(l01, l2, 0u, 0u);
                } else {
                    hv4 = make_uint4(0u, 0u, 0u, 0u);
                    lv4 = make_uint4(0u, 0u, 0u, 0u);
                }
                unsigned ch = (unsigned)(c ^ rx);
                unsigned cl = (unsigned)((KC + c) ^ rx);
                *(uint4*)(Asm + rowOff + ch*16) = hv4;
                *(uint4*)(Asm + rowOff + cl*16) = lv4;
            }
        } else {
            const float* srcf = ((LAYER == 1) ? g_y1 : g_y2) + (rowBase + row) * 64;
            #pragma unroll
            for (int j = 0; j < HC; j++) {
                int c  = half*HC + j;
                int k0 = c*8;
                float4 v0 = *(const float4*)(srcf + k0);
                float4 v1 = *(const float4*)(srcf + k0 + 4);
                float f[8] = {v0.x,v0.y,v0.z,v0.w,v1.x,v1.y,v1.z,v1.w};
                #pragma unroll
                for (int i = 0; i < 8; i++)
                    f[i] = fmaxf(fmaf(f[i], sS[k0+i], sT[k0+i]), 0.f);
                unsigned hv[4], lv[4];
                #pragma unroll
                for (int q = 0; q < 4; q++) {
                    float f0 = f[2*q], f1 = f[2*q+1];
                    unsigned h = cvt2bf(f1, f0);
                    float h0f = __uint_as_float(h << 16);
                    float h1f = __uint_as_float(h & 0xffff0000u);
                    hv[q] = h;
                    lv[q] = cvt2bf(f1 - h1f, f0 - h0f);
                }
                unsigned ch = (unsigned)(c ^ rx);
                unsigned cl = (unsigned)((KC + c) ^ rx);
                *(uint4*)(Asm + rowOff + ch*16) = make_uint4(hv[0],hv[1],hv[2],hv[3]);
                *(uint4*)(Asm + rowOff + cl*16) = make_uint4(lv[0],lv[1],lv[2],lv[3]);
            }
        }
    }
    // ---- B copy: hi/lo images -> swizzled smem ----
    {
        const __nv_bfloat16* Wh = (LAYER==0) ? g_Wh0 : (LAYER==1) ? g_Wh1 : g_Wh2;
        const __nv_bfloat16* Wl = (LAYER==0) ? g_Wl0 : (LAYER==1) ? g_Wl1 : g_Wl2;
        for (int i = tid; i < CO * 2 * KC; i += 256) {
            int n = i / (2*KC), c = i % (2*KC);
            const __nv_bfloat16* src = (c < KC) ? (Wh + n*K + c*8)
                                                : (Wl + n*K + (c - KC)*8);
            uint4 v = *(const uint4*)src;
            unsigned cs = (unsigned)(c ^ (n & 7));
            *(uint4*)(Bsm + (unsigned)n*(ST*16) + cs*16) = v;
        }
    }
    __syncthreads();

    // ---- MMA main loop ----
    const uint32_t Abase = smem_u32(Asm);
    const uint32_t Bbase = smem_u32(Bsm);
    const int warp = tid >> 5, lane = tid & 31;
    const int wm = warp >> 1, wn = warp & 1;
    const int Rw = wm*32, Cw = wn*WCOLS;

    const int arow = lane & 15;
    const uint32_t aAddr0 = Abase + (unsigned)(Rw + arow)      * (ST*16);
    const uint32_t aAddr1 = Abase + (unsigned)(Rw + 16 + arow) * (ST*16);
    const unsigned axr = (unsigned)(arow & 7);
    const unsigned aHi = (unsigned)(lane >> 4);
    const int nro  = (lane & 7) + ((lane & 16) >> 1);
    const unsigned bxr = (unsigned)(nro & 7);
    const unsigned bHi = (unsigned)((lane >> 3) & 1);

    float cc[2][NT][4];
    #pragma unroll
    for (int mi = 0; mi < 2; mi++)
        #pragma unroll
        for (int ni = 0; ni < NT; ni++)
            #pragma unroll
            for (int q = 0; q < 4; q++) cc[mi][ni][q] = 0.f;

    #pragma unroll
    for (int s = 0; s < 3; s++) {
        const unsigned sa = (s == 1) ? KC : 0;
        const unsigned sbc = (s == 2) ? KC : 0;
        #pragma unroll
        for (int kc = 0; kc < NKCH; kc++) {
            unsigned ca = sa + kc*2 + aHi;
            unsigned a0r[4], a1r[4];
            ldsm4(a0r, aAddr0 + ((ca ^ axr) << 4));
            ldsm4(a1r, aAddr1 + ((ca ^ axr) << 4));
            unsigned cb = sbc + kc*2 + bHi;
            #pragma unroll
            for (int ntp = 0; ntp < NT/2; ntp++) {
                int brow = Cw + ntp*16 + nro;
                unsigned br[4];
                ldsm4(br, Bbase + (unsigned)brow*(ST*16) + ((cb ^ bxr) << 4));
                mma16816(cc[0][ntp*2],   a0r, br[0], br[1]);
                mma16816(cc[0][ntp*2+1], a0r, br[2], br[3]);
                mma16816(cc[1][ntp*2],   a1r, br[0], br[1]);
                mma16816(cc[1][ntp*2+1], a1r, br[2], br[3]);
            }
        }
    }

    // ---- epilogue: bias, Y store, stats, L2 max ----
    float* Y = (LAYER == 0) ? g_y1 : g_y2;
    const int tq = lane >> 2, tr = lane & 3;
    #pragma unroll
    for (int ni = 0; ni < NT; ni++) {
        int cn = Cw + ni*8 + tr*2;
        float b0 = sb[cn], b1 = sb[cn+1];
        float s0=0.f, s1=0.f, q0=0.f, q1=0.f, m0=-3.4e38f, m1=-3.4e38f;
        #pragma unroll
        for (int mi = 0; mi < 2; mi++) {
            float d0 = cc[mi][ni][0] + b0;
            float d1 = cc[mi][ni][1] + b1;
            float d2 = cc[mi][ni][2] + b0;
            float d3 = cc[mi][ni][3] + b1;
            if (LAYER < 2) {
                size_t r = rowBase + Rw + mi*16 + tq;
                *(float2*)&Y[r*64 + cn]     = make_float2(d0, d1);
                *(float2*)&Y[(r+8)*64 + cn] = make_float2(d2, d3);
            }
            s0 += d0 + d2;  s1 += d1 + d3;
            q0 += d0*d0 + d2*d2;  q1 += d1*d1 + d3*d3;
            m0 = fmaxf(m0, fmaxf(d0, d2));  m1 = fmaxf(m1, fmaxf(d1, d3));
        }
        #pragma unroll
        for (int o = 4; o <= 16; o <<= 1) {
            s0 += __shfl_xor_sync(0xffffffffu, s0, o);
            s1 += __shfl_xor_sync(0xffffffffu, s1, o);
            q0 += __shfl_xor_sync(0xffffffffu, q0, o);
            q1 += __shfl_xor_sync(0xffffffffu, q1, o);
            if (LAYER == 2) {
                m0 = fmaxf(m0, __shfl_xor_sync(0xffffffffu, m0, o));
                m1 = fmaxf(m1, __shfl_xor_sync(0xffffffffu, m1, o));
            }
        }
        if (lane < 4) {
            atomicAdd(&ssum[cn],   s0);
            atomicAdd(&ssum[cn+1], s1);
            atomicAdd(&ssq[cn],    q0);
            atomicAdd(&ssq[cn+1],  q1);
            if (LAYER == 2) {
                int bm = (int)(rowBase >> 5) + wm;
                size_t o0 = ((size_t)(bm >> 11)*128 + (unsigned)cn)*2048 + (unsigned)(bm & 2047);
                g_maxf[o0]        = m0;
                g_maxf[o0 + 2048] = m1;
            }
        }
    }
    __syncthreads();
    if (tid < CO) {
        atomicAdd(&g_sum[LAYER][tid], (double)ssum[tid]);
        atomicAdd(&g_sq [LAYER][tid], (double)ssq [tid]);
    }
}

// ---------------- BN stats -> scale/shift --------------------------------
__global__ void finalize_kernel(int L, const float* __restrict__ g,
                                const float* __restrict__ beta, int Co)
{
    int c = threadIdx.x;
    if (c >= Co) return;
    double inv = 1.0 / (double)NROWS;
    double mu  = g_sum[L][c] * inv;
    double var = g_sq[L][c] * inv - mu*mu;
    if (var < 0.0) var = 0.0;
    float s = g[c] / sqrtf((float)var + BN_EPS);
    g_s[L][c] = s;
    g_t[L][c] = fmaf(-(float)mu, s, beta[c]);
}

// ---------------- BN+ReLU on pre-pooled max, transposed layout -----------
__global__ void maxpool_kernel(float* __restrict__ out)
{
    int i = blockIdx.x * blockDim.x + threadIdx.x;   // over B*128*M = 2M
    int c = (i >> 11) & 127;
    float s = g_s[2][c], t = g_t[2][c];
    out[(size_t)Bb*Mm*3 + i] = fmaxf(fmaf(g_maxf[i], s, t), 0.f);
}

// ---------------- launch ---------------------------------------------------
extern "C" void kernel_launch(void* const* d_in, const int* in_sizes, int n_in,
                              void* d_out, int out_size)
{
    (void)in_sizes; (void)n_in; (void)out_size;
    const float* xyz  = (const float*)d_in[0];
    const float* feats= (const float*)d_in[1];
    const float* W1   = (const float*)d_in[2];
    const float* b1   = (const float*)d_in[3];
    const float* g1   = (const float*)d_in[4];
    const float* be1  = (const float*)d_in[5];
    const float* W2   = (const float*)d_in[6];
    const float* b2   = (const float*)d_in[7];
    const float* g2   = (const float*)d_in[8];
    const float* be2  = (const float*)d_in[9];
    const float* W3   = (const float*)d_in[10];
    const float* b3   = (const float*)d_in[11];
    const float* g3   = (const float*)d_in[12];
    const float* be3  = (const float*)d_in[13];
    float* out = (float*)d_out;
    const float* centers = out;   // knn writes centers into d_out[0 : B*M*3)

    const int SM0 = 128*24*16 + 64*24*16;     // 73728
    const int SM1 = 128*16*16 + 64*16*16;     // 49152
    const int SM2 = 128*16*16 + 128*16*16;    // 65536
    cudaFuncSetAttribute(mma_kernel<0>, cudaFuncAttributeMaxDynamicSharedMemorySize, SM0);
    cudaFuncSetAttribute(mma_kernel<1>, cudaFuncAttributeMaxDynamicSharedMemorySize, SM1);
    cudaFuncSetAttribute(mma_kernel<2>, cudaFuncAttributeMaxDynamicSharedMemorySize, SM2);

    const int KNN_SMEM = 1024*4 + 4*CAPQ*4*2;   // hist + cand arrays = 45056 B

    prep_kernel<<<68, 256>>>(W1, W2, W3);
    pad_kernel<<<(Bb*Pp)/256, 256>>>(xyz);
    transpose_kernel<<<dim3(Pp/32, CIN/32, Bb), dim3(32, 8)>>>(feats);
    knn_kernel<<<Bb*512, 256, KNN_SMEM>>>(out);

    mma_kernel<0><<<NROWS/128, 256, SM0>>>(b1, centers);
    finalize_kernel<<<1, 64>>>(0, g1, be1, 64);
    mma_kernel<1><<<NROWS/128, 256, SM1>>>(b2, centers);
    finalize_kernel<<<1, 64>>>(1, g2, be2, 64);
    mma_kernel<2><<<NROWS/128, 256, SM2>>>(b3, centers);
    finalize_kernel<<<1, 128>>>(2, g3, be3, 128);

    maxpool_kernel<<<(Bb*Mm*128)/256, 256>>>(out);
}

// round 15
// speedup vs baseline: 1.0041x; 1.0041x over previous
#include <cuda_runtime.h>
#include <cuda_bf16.h>
#include <cstdint>

#define Bb   8
#define Pp   8192
#define CIN  64
#define KK   32
#define Mm   2048
#define NROWS (Bb*Mm*KK)     // 524288
#define BN_EPS 1e-5f

// ---------------- scratch (device globals; no allocation) ----------------
__device__ __align__(128) __nv_bfloat16 g_fh[(size_t)Bb*Pp*CIN]; // feats hi (8 MB)
__device__ __align__(128) __nv_bfloat16 g_fl[(size_t)Bb*Pp*CIN]; // feats lo (8 MB)
__device__ __align__(128) float4 g_xyz4[(size_t)Bb*Pp];          // (x,y,z,|x|^2)
__device__ __align__(128) int    g_sel[(size_t)NROWS];           // 2 MB
__device__ __align__(128) float  g_y1[(size_t)NROWS*64];         // 134 MB
__device__ __align__(128) float  g_y2[(size_t)NROWS*64];         // 134 MB
__device__ __align__(128) float  g_maxf[(size_t)Bb*128*Mm];      // 8 MB
// weight hi/lo bf16 images (unswizzled, K-major rows)
__device__ __align__(128) __nv_bfloat16 g_Wh0[64*80],  g_Wl0[64*80];
__device__ __align__(128) __nv_bfloat16 g_Wh1[64*64],  g_Wl1[64*64];
__device__ __align__(128) __nv_bfloat16 g_Wh2[128*64], g_Wl2[128*64];
__device__ double g_sum[3][128];
__device__ double g_sq[3][128];
__device__ float  g_s[3][128];
__device__ float  g_t[3][128];

// ---------------- small helpers ------------------------------------------
__device__ __forceinline__ uint32_t smem_u32(const void* p) {
    uint32_t a;
    asm("{ .reg .u64 t; cvta.to.shared.u64 t, %1; cvt.u32.u64 %0, t; }" : "=r"(a) : "l"(p));
    return a;
}
__device__ __forceinline__ unsigned pkb(__nv_bfloat16 a, __nv_bfloat16 b) {
    __nv_bfloat162 t; t.x = a; t.y = b;
    return *(unsigned*)&t;
}
__device__ __forceinline__ void wsplit(float w, __nv_bfloat16& h, __nv_bfloat16& l) {
    h = __float2bfloat16(w);
    l = __float2bfloat16(w - __bfloat162float(h));
}
__device__ __forceinline__ unsigned cvt2bf(float hi, float lo) {
    unsigned r;
    asm("cvt.rn.bf16x2.f32 %0, %1, %2;" : "=r"(r) : "f"(hi), "f"(lo));
    return r;
}
__device__ __forceinline__ void ldsm4(unsigned* r, uint32_t addr) {
    asm volatile("ldmatrix.sync.aligned.m8n8.x4.shared.b16 {%0,%1,%2,%3}, [%4];"
        : "=r"(r[0]), "=r"(r[1]), "=r"(r[2]), "=r"(r[3]) : "r"(addr));
}
__device__ __forceinline__ void mma16816(float* c, const unsigned* a,
                                         unsigned b0, unsigned b1) {
    asm volatile("mma.sync.aligned.m16n8k16.row.col.f32.bf16.bf16.f32 "
        "{%0,%1,%2,%3}, {%4,%5,%6,%7}, {%8,%9}, {%0,%1,%2,%3};"
        : "+f"(c[0]), "+f"(c[1]), "+f"(c[2]), "+f"(c[3])
        : "r"(a[0]), "r"(a[1]), "r"(a[2]), "r"(a[3]), "r"(b0), "r"(b1));
}
__device__ __forceinline__ unsigned mapu(float d) {
    unsigned u = __float_as_uint(d);
    return u ^ ((unsigned)(((int)u) >> 31) | 0x80000000u);
}
// packed f32x2 (exact per-lane fp32 rn)
#define PACK2(d, lo, hi)    asm("mov.b64 %0, {%1,%2};" : "=l"(d) : "f"(lo), "f"(hi))
#define UNPACK2F(lo, hi, v) asm("mov.b64 {%0,%1}, %2;" : "=f"(lo), "=f"(hi) : "l"(v))
#define MUL2(d, a, b)       asm("mul.rn.f32x2 %0, %1, %2;" : "=l"(d) : "l"(a), "l"(b))
#define ADD2(d, a, b)       asm("add.rn.f32x2 %0, %1, %2;" : "=l"(d) : "l"(a), "l"(b))

// ------- prep: zero stats + bf16 hi/lo weight images + xyz pad ------------
__global__ void prep_kernel(const float* __restrict__ W1,
                            const float* __restrict__ W2,
                            const float* __restrict__ W3,
                            const float* __restrict__ xyz)
{
    int tid = blockIdx.x * blockDim.x + threadIdx.x;
    if (tid < 384) { ((double*)g_sum)[tid] = 0.0; ((double*)g_sq)[tid] = 0.0; }
    if (tid < 5120 + 4096 + 8192) {
        float w;
        __nv_bfloat16 *ph, *pl;
        int idx;
        if (tid < 5120) {                   // W0: [64][80] = feats(64)+xyz(3)+pad
            int n = tid / 80, k = tid % 80;
            if (k < 64)      w = W1[n*67 + k + 3];
            else if (k < 67) w = W1[n*67 + (k - 64)];
            else             w = 0.f;
            ph = g_Wh0; pl = g_Wl0; idx = tid;
        } else if (tid < 9216) {            // W1: [64][64]
            int t = tid - 5120;
            w = W2[t];
            ph = g_Wh1; pl = g_Wl1; idx = t;
        } else {                            // W2: [128][64]
            int t = tid - 9216;
            w = W3[t];
            ph = g_Wh2; pl = g_Wl2; idx = t;
        }
        __nv_bfloat16 h, l; wsplit(w, h, l);
        ph[idx] = h; pl[idx] = l;
    }
    if (tid < Bb*Pp) {                      // xyz -> float4 (x,y,z,|x|^2)
        const float* s = xyz + (size_t)tid*3;
        float x = s[0], y = s[1], z = s[2];
        float n = __fadd_rn(__fadd_rn(__fmul_rn(x,x), __fmul_rn(y,y)), __fmul_rn(z,z));
        g_xyz4[tid] = make_float4(x, y, z, n);
    }
}

// ---------------- feats (B,C,P) -> bf16 hi/lo (B,P,C) ---------------------
__global__ void transpose_kernel(const float* __restrict__ f)
{
    __shared__ float tile[32][33];
    int b  = blockIdx.z;
    int c0 = blockIdx.y * 32;
    int p0 = blockIdx.x * 32;
    int tx = threadIdx.x, ty = threadIdx.y;
    #pragma unroll
    for (int i = ty; i < 32; i += 8)
        tile[i][tx] = f[((size_t)b*CIN + c0 + i)*Pp + p0 + tx];
    __syncthreads();
    #pragma unroll
    for (int i = ty; i < 32; i += 8) {
        float v = tile[tx][i];
        __nv_bfloat16 h, l; wsplit(v, h, l);
        size_t o = ((size_t)b*Pp + p0 + i)*CIN + c0 + tx;
        g_fh[o] = h;
        g_fl[o] = l;
    }
}

// --- KNN: 4 q/block, 3-pass sample pivot, exact packed sweep, par. tail ---
#define CAPQ 1280
__global__ void __launch_bounds__(256, 4) knn_kernel(float* __restrict__ centers_out)
{
    int blk = blockIdx.x;          // 0..4095
    int b   = blk >> 9;
    int mbase = (blk & 511) * 4;

    extern __shared__ char sm[];
    unsigned* hist    = (unsigned*)sm;                 // 1024 bins (4 x 256)
    unsigned* cand_dm = hist + 1024;                   // 4*CAPQ
    int*      cand_id = (int*)(cand_dm + 4*CAPQ);      // 4*CAPQ
    __shared__ float    ctr[4][4];
    __shared__ float    sTf[4];
    __shared__ unsigned s_prefix[4];
    __shared__ int s_remaining[4], s_ncand[4], s_cnt[4];
    __shared__ int s_min4[4], s_last4[4];
    __shared__ int s_maxrem;

    int tid  = threadIdx.x;
    int wid  = tid >> 5;
    int lane = tid & 31;
    const float4* X4 = g_xyz4 + ((size_t)b << 13);

    if (tid < 4) {
        int m = mbase + tid;
        int ci = (m == 2047) ? 8191
               : (int)(__fmul_rn(8191.0f, __fdiv_rn((float)m, 2047.0f)));
        float4 cp = X4[ci];
        ctr[tid][0] = cp.x; ctr[tid][1] = cp.y; ctr[tid][2] = cp.z; ctr[tid][3] = cp.w;
        float* co = centers_out + (size_t)(b*2048 + m)*3;
        co[0] = cp.x; co[1] = cp.y; co[2] = cp.z;
        s_prefix[tid] = 0u; s_remaining[tid] = KK;
        s_ncand[tid] = 0; s_cnt[tid] = 0; s_last4[tid] = -1;
    }
    __syncthreads();
    float cxq[4], cyq[4], czq[4], cnq[4];
    #pragma unroll
    for (int q = 0; q < 4; q++) {
        cxq[q] = ctr[q][0]; cyq[q] = ctr[q][1]; czq[q] = ctr[q][2]; cnq[q] = ctr[q][3];
    }
    auto distq = [&](int q, float4 X) -> float {
        float dt = __fadd_rn(__fadd_rn(__fmul_rn(cxq[q],X.x), __fmul_rn(cyq[q],X.y)),
                             __fmul_rn(czq[q],X.z));
        return __fsub_rn(__fadd_rn(cnq[q], X.w), __fmul_rn(2.0f, dt));
    };
    auto hadd = [&](bool ok, unsigned bkt) {
        unsigned mask = __ballot_sync(0xffffffffu, ok);
        if (ok) {
            unsigned peers = __match_any_sync(mask, bkt);
            if ((peers & ((1u << lane) - 1u)) == 0u)
                atomicAdd(&hist[bkt], __popc(peers));
        }
    };
    auto scanq = [&](int q, int base) {
        unsigned cum[8];
        unsigned run = 0;
        #pragma unroll
        for (int i = 0; i < 8; i++) { run += hist[base + lane*8 + i]; cum[i] = run; }
        unsigned tot = run;
        unsigned off = tot;
        #pragma unroll
        for (int dd = 1; dd < 32; dd <<= 1) {
            unsigned v = __shfl_up_sync(0xffffffffu, off, dd);
            if (lane >= dd) off += v;
        }
        off -= tot;
        unsigned rem = (unsigned)s_remaining[q];
        #pragma unroll
        for (int i = 0; i < 8; i++) {
            unsigned prev = off + (i ? cum[i-1] : 0u);
            unsigned cu   = off + cum[i];
            if (prev < rem && cu >= rem) {
                s_prefix[q] = (s_prefix[q] << 8) | (unsigned)(lane*8 + i);
                s_remaining[q] = (int)(rem - prev);
            }
        }
    };

    // ---- sample phase: 512 points {16t,16t+1}; 3 passes (24-bit pivot) ----
    unsigned sd[4][2];
    {
        float4 A = __ldg(X4 + 16*tid);
        float4 Bp = __ldg(X4 + 16*tid + 1);
        #pragma unroll
        for (int q = 0; q < 4; q++) {
            sd[q][0] = mapu(distq(q, A));
            sd[q][1] = mapu(distq(q, Bp));
        }
    }
    for (int pass = 0; pass < 3; pass++) {
        #pragma unroll
        for (int t = tid; t < 1024; t += 256) hist[t] = 0;
        __syncthreads();
        unsigned prefq[4];
        #pragma unroll
        for (int q = 0; q < 4; q++) prefq[q] = s_prefix[q];
        int sh = 24 - 8*pass;
        #pragma unroll
        for (int q = 0; q < 4; q++) {
            #pragma unroll
            for (int k = 0; k < 2; k++) {
                bool ok = (pass == 0) || ((sd[q][k] >> (sh + 8)) == prefq[q]);
                hadd(ok, (unsigned)(q*256) + ((sd[q][k] >> sh) & 255u));
            }
        }
        __syncthreads();
        if (wid < 4) scanq(wid, wid*256);
        __syncthreads();
    }
    if (tid < 4) {
        // pivot = TOP of the 24-bit bucket holding the sample kth (upper bound)
        unsigned mv = (s_prefix[tid] << 8) | 0xFFu;
        unsigned u  = (mv & 0x80000000u) ? (mv ^ 0x80000000u) : ~mv;
        sTf[tid] = __uint_as_float(u);
        s_prefix[tid] = 0u; s_remaining[tid] = KK;
    }
    __syncthreads();
    float Tf[4] = {sTf[0], sTf[1], sTf[2], sTf[3]};

    // packed query constants: {q0,q1} and {q2,q3}
    unsigned long long qx01, qx23, qy01, qy23, qz01, qz23, qn01, qn23;
    PACK2(qx01, cxq[0], cxq[1]); PACK2(qx23, cxq[2], cxq[3]);
    PACK2(qy01, cyq[0], cyq[1]); PACK2(qy23, cyq[2], cyq[3]);
    PACK2(qz01, czq[0], czq[1]); PACK2(qz23, czq[2], czq[3]);
    PACK2(qn01, cnq[0], cnq[1]); PACK2(qn23, cnq[2], cnq[3]);

    // ---- main sweep: 1 LDG.128/point, packed f32x2 exact distances ----
    #pragma unroll 4
    for (int jj = 0; jj < 32; jj++) {
        int p = tid + jj*256;
        float4 X = __ldg(X4 + p);
        unsigned long long Xx, Xy, Xz, Xw;
        PACK2(Xx, X.x, X.x); PACK2(Xy, X.y, X.y);
        PACK2(Xz, X.z, X.z); PACK2(Xw, X.w, X.w);
        unsigned long long t, u, d01, d23;
        MUL2(t, qx01, Xx); MUL2(u, qy01, Xy); ADD2(t, t, u);
        MUL2(u, qz01, Xz); ADD2(t, t, u);
        ADD2(t, t, t); t ^= 0x8000000080000000ULL;
        ADD2(u, qn01, Xw); ADD2(d01, u, t);
        MUL2(t, qx23, Xx); MUL2(u, qy23, Xy); ADD2(t, t, u);
        MUL2(u, qz23, Xz); ADD2(t, t, u);
        ADD2(t, t, t); t ^= 0x8000000080000000ULL;
        ADD2(u, qn23, Xw); ADD2(d23, u, t);
        float d0, d1, d2, d3;
        UNPACK2F(d0, d1, d01);
        UNPACK2F(d2, d3, d23);
        if (d0 <= Tf[0]) {
            int pos = atomicAdd(&s_ncand[0], 1);
            if (pos < CAPQ) { cand_dm[0*CAPQ + pos] = mapu(d0); cand_id[0*CAPQ + pos] = p; }
        }
        if (d1 <= Tf[1]) {
            int pos = atomicAdd(&s_ncand[1], 1);
            if (pos < CAPQ) { cand_dm[1*CAPQ + pos] = mapu(d1); cand_id[1*CAPQ + pos] = p; }
        }
        if (d2 <= Tf[2]) {
            int pos = atomicAdd(&s_ncand[2], 1);
            if (pos < CAPQ) { cand_dm[2*CAPQ + pos] = mapu(d2); cand_id[2*CAPQ + pos] = p; }
        }
        if (d3 <= Tf[3]) {
            int pos = atomicAdd(&s_ncand[3], 1);
            if (pos < CAPQ) { cand_dm[3*CAPQ + pos] = mapu(d3); cand_id[3*CAPQ + pos] = p; }
        }
    }
    __syncthreads();

    int nc[4];
    bool anyofl = false;
    #pragma unroll
    for (int q = 0; q < 4; q++) { nc[q] = s_ncand[q]; anyofl |= (nc[q] > CAPQ); }

    // ---- candidate radix: 4 queries in PARALLEL (exact cand_dm stored) ----
    for (int pass = 0; pass < 4; pass++) {
        #pragma unroll
        for (int t = tid; t < 1024; t += 256) hist[t] = 0;
        __syncthreads();
        int sh = 24 - 8*pass;
        #pragma unroll
        for (int q = 0; q < 4; q++) {
            if (nc[q] > CAPQ) continue;
            unsigned pref = s_prefix[q];
            for (int it = 0; it*256 < nc[q]; it++) {
                int t = it*256 + tid;
                unsigned dv = (t < nc[q]) ? cand_dm[q*CAPQ + t] : 0u;
                bool ok = (t < nc[q]) && ((pass == 0) || ((dv >> (sh + 8)) == pref));
                hadd(ok, (unsigned)(q*256) + ((dv >> sh) & 255u));
            }
        }
        __syncthreads();
        if (wid < 4 && nc[wid] <= CAPQ) scanq(wid, wid*256);
        __syncthreads();
    }

    // ---- selection: 4 queries in parallel ----
    #pragma unroll
    for (int q = 0; q < 4; q++) {
        if (nc[q] > CAPQ) continue;
        unsigned thr = s_prefix[q];
        int* selg = g_sel + (size_t)(b*2048 + mbase + q) * KK;
        for (int it = 0; it*256 < nc[q]; it++) {
            int t = it*256 + tid;
            if (t < nc[q] && cand_dm[q*CAPQ + t] < thr) {
                int s = atomicAdd(&s_cnt[q], 1);
                selg[s] = cand_id[q*CAPQ + t];
            }
        }
    }
    __syncthreads();
    if (tid == 0) {
        int mr = 0;
        for (int q = 0; q < 4; q++)
            if (nc[q] <= CAPQ && s_remaining[q] > mr) mr = s_remaining[q];
        s_maxrem = mr;
    }
    __syncthreads();
    int maxrem = s_maxrem;
    for (int r = 0; r < maxrem; r++) {
        if (tid < 4) s_min4[tid] = 0x7fffffff;
        __syncthreads();
        #pragma unroll
        for (int q = 0; q < 4; q++) {
            if (nc[q] > CAPQ || r >= s_remaining[q]) continue;
            unsigned thr = s_prefix[q];
            int last = s_last4[q];
            for (int it = 0; it*256 < nc[q]; it++) {
                int t = it*256 + tid;
                if (t < nc[q] && cand_dm[q*CAPQ + t] == thr && cand_id[q*CAPQ + t] > last)
                    atomicMin(&s_min4[q], cand_id[q*CAPQ + t]);
            }
        }
        __syncthreads();
        if (tid < 4) {
            int q = tid;
            if (nc[q] <= CAPQ && r < s_remaining[q]) {
                int* selg = g_sel + (size_t)(b*2048 + mbase + q) * KK;
                selg[s_cnt[q] + r] = s_min4[q];
                s_last4[q] = s_min4[q];
            }
        }
        __syncthreads();
    }

    // ---- exact fallback for overflow queries (rare) ----
    if (anyofl) {
        for (int q = 0; q < 4; q++) {
            if (nc[q] <= CAPQ) continue;
            __syncthreads();
            if (tid == 0) { s_prefix[q] = 0u; s_remaining[q] = KK; s_cnt[q] = 0; s_last4[q] = -1; }
            __syncthreads();
            for (int pass = 0; pass < 4; pass++) {
                hist[tid] = 0;
                __syncthreads();
                unsigned pref = s_prefix[q];
                int sh = 24 - 8*pass;
                for (int jj = 0; jj < 32; jj++) {
                    float4 X = __ldg(X4 + tid + jj*256);
                    unsigned u = mapu(distq(q, X));
                    bool ok = (pass == 0) || ((u >> (sh + 8)) == pref);
                    hadd(ok, (u >> sh) & 255u);
                }
                __syncthreads();
                if (wid == 0) scanq(q, 0);
                __syncthreads();
            }
            unsigned thr = s_prefix[q];
            int rem = s_remaining[q];
            int* selg = g_sel + (size_t)(b*2048 + mbase + q) * KK;
            for (int jj = 0; jj < 32; jj++) {
                int p = tid + jj*256;
                float4 X = __ldg(X4 + p);
                if (mapu(distq(q, X)) < thr) {
                    int s = atomicAdd(&s_cnt[q], 1);
                    selg[s] = p;
                }
            }
            __syncthreads();
            int base = s_cnt[q];
            for (int r = 0; r < rem; r++) {
                if (tid == 0) s_min4[0] = 0x7fffffff;
                __syncthreads();
                int last = s_last4[q];
                for (int jj = 0; jj < 32; jj++) {
                    int p = tid + jj*256;
                    float4 X = __ldg(X4 + p);
                    if (mapu(distq(q, X)) == thr && p > last) atomicMin(&s_min4[0], p);
                }
                __syncthreads();
                if (tid == 0) { selg[base + r] = s_min4[0]; s_last4[q] = s_min4[0]; }
                __syncthreads();
            }
        }
    }
}

// ---------------- bf16x3 GEMM via mma.sync (HMMA tensor pipe) -------------
template<int LAYER>
__global__ void __launch_bounds__(256) mma_kernel(const float* __restrict__ bias,
                                                  const float* __restrict__ centers)
{
    constexpr int CO    = (LAYER == 2) ? 128 : 64;
    constexpr int K     = (LAYER == 0) ? 80 : 64;
    constexpr int KC    = K / 8;
    constexpr int NKCH  = K / 16;
    constexpr int ST    = (LAYER == 0) ? 24 : 16;
    constexpr int ASZ   = 128 * ST * 16;
    constexpr int WCOLS = CO / 2;
    constexpr int NT    = WCOLS / 8;
    constexpr int HC    = KC / 2;

    extern __shared__ __align__(16) char dyn[];
    char* Asm = dyn;
    char* Bsm = dyn + ASZ;
    __shared__ float sb[CO], ssum[CO], ssq[CO];
    __shared__ float sS[64], sT[64];

    const int tid = threadIdx.x;
    const size_t rowBase = (size_t)blockIdx.x * 128;
    const int bBat = (int)(rowBase >> 16);

    if (tid < CO) { sb[tid] = bias[tid]; ssum[tid] = 0.f; ssq[tid] = 0.f; }
    if (LAYER > 0 && tid < 64) { sS[tid] = g_s[LAYER-1][tid]; sT[tid] = g_t[LAYER-1][tid]; }
    __syncthreads();

    // ---- A build: 2 threads per row ----
    {
        int row = tid >> 1, half = tid & 1;
        int rx = row & 7;
        unsigned rowOff = (unsigned)row * (ST*16);
        if (LAYER == 0) {
            int p = g_sel[rowBase + row];
            const uint4* FH = (const uint4*)g_fh + (((size_t)bBat << 13) + (unsigned)p) * 8;
            const uint4* FL = (const uint4*)g_fl + (((size_t)bBat << 13) + (unsigned)p) * 8;
            #pragma unroll
            for (int j = 0; j < HC; j++) {
                int c = half*HC + j;
                uint4 hv4, lv4;
                if (c < 8) {
                    hv4 = __ldg(FH + c);
                    lv4 = __ldg(FL + c);
                } else if (c == 8) {
                    float4 X = g_xyz4[((size_t)bBat << 13) + (unsigned)p];
                    int bm = (int)((rowBase + row) >> 5);
                    float dx = X.x - centers[bm*3 + 0];
                    float dy = X.y - centers[bm*3 + 1];
                    float dz = X.z - centers[bm*3 + 2];
                    unsigned h01 = cvt2bf(dy, dx);
                    float h0f = __uint_as_float(h01 << 16);
                    float h1f = __uint_as_float(h01 & 0xffff0000u);
                    unsigned l01 = cvt2bf(dy - h1f, dx - h0f);
                    unsigned h2 = cvt2bf(0.f, dz);
                    float h2f = __uint_as_float(h2 << 16);
                    unsigned l2 = cvt2bf(0.f, dz - h2f);
                    hv4 = make_uint4(h01, h2, 0u, 0u);
                    lv4 = make_uint4(l01, l2, 0u, 0u);
                } else {
                    hv4 = make_uint4(0u, 0u, 0u, 0u);
                    lv4 = make_uint4(0u, 0u, 0u, 0u);
                }
                unsigned ch = (unsigned)(c ^ rx);
                unsigned cl = (unsigned)((KC + c) ^ rx);
                *(uint4*)(Asm + rowOff + ch*16) = hv4;
                *(uint4*)(Asm + rowOff + cl*16) = lv4;
            }
        } else {
            const float* srcf = ((LAYER == 1) ? g_y1 : g_y2) + (rowBase + row) * 64;
            #pragma unroll
            for (int j = 0; j < HC; j++) {
                int c  = half*HC + j;
                int k0 = c*8;
                float4 v0 = *(const float4*)(srcf + k0);
                float4 v1 = *(const float4*)(srcf + k0 + 4);
                float f[8] = {v0.x,v0.y,v0.z,v0.w,v1.x,v1.y,v1.z,v1.w};
                #pragma unroll
                for (int i = 0; i < 8; i++)
                    f[i] = fmaxf(fmaf(f[i], sS[k0+i], sT[k0+i]), 0.f);
                unsigned hv[4], lv[4];
                #pragma unroll
                for (int q = 0; q < 4; q++) {
                    float f0 = f[2*q], f1 = f[2*q+1];
                    unsigned h = cvt2bf(f1, f0);
                    float h0f = __uint_as_float(h << 16);
                    float h1f = __uint_as_float(h & 0xffff0000u);
                    hv[q] = h;
                    lv[q] = cvt2bf(f1 - h1f, f0 - h0f);
                }
                unsigned ch = (unsigned)(c ^ rx);
                unsigned cl = (unsigned)((KC + c) ^ rx);
                *(uint4*)(Asm + rowOff + ch*16) = make_uint4(hv[0],hv[1],hv[2],hv[3]);
                *(uint4*)(Asm + rowOff + cl*16) = make_uint4(lv[0],lv[1],lv[2],lv[3]);
            }
        }
    }
    // ---- B copy: hi/lo images -> swizzled smem ----
    {
        const __nv_bfloat16* Wh = (LAYER==0) ? g_Wh0 : (LAYER==1) ? g_Wh1 : g_Wh2;
        const __nv_bfloat16* Wl = (LAYER==0) ? g_Wl0 : (LAYER==1) ? g_Wl1 : g_Wl2;
        for (int i = tid; i < CO * 2 * KC; i += 256) {
            int n = i / (2*KC), c = i % (2*KC);
            const __nv_bfloat16* src = (c < KC) ? (Wh + n*K + c*8)
                                                : (Wl + n*K + (c - KC)*8);
            uint4 v = *(const uint4*)src;
            unsigned cs = (unsigned)(c ^ (n & 7));
            *(uint4*)(Bsm + (unsigned)n*(ST*16) + cs*16) = v;
        }
    }
    __syncthreads();

    // ---- MMA main loop ----
    const uint32_t Abase = smem_u32(Asm);
    const uint32_t Bbase = smem_u32(Bsm);
    const int warp = tid >> 5, lane = tid & 31;
    const int wm = warp >> 1, wn = warp & 1;
    const int Rw = wm*32, Cw = wn*WCOLS;

    const int arow = lane & 15;
    const uint32_t aAddr0 = Abase + (unsigned)(Rw + arow)      * (ST*16);
    const uint32_t aAddr1 = Abase + (unsigned)(Rw + 16 + arow) * (ST*16);
    const unsigned axr = (unsigned)(arow & 7);
    const unsigned aHi = (unsigned)(lane >> 4);
    const int nro  = (lane & 7) + ((lane & 16) >> 1);
    const unsigned bxr = (unsigned)(nro & 7);
    const unsigned bHi = (unsigned)((lane >> 3) & 1);

    float cc[2][NT][4];
    #pragma unroll
    for (int mi = 0; mi < 2; mi++)
        #pragma unroll
        for (int ni = 0; ni < NT; ni++)
            #pragma unroll
            for (int q = 0; q < 4; q++) cc[mi][ni][q] = 0.f;

    #pragma unroll
    for (int s = 0; s < 3; s++) {
        const unsigned sa = (s == 1) ? KC : 0;
        const unsigned sbc = (s == 2) ? KC : 0;
        #pragma unroll
        for (int kc = 0; kc < NKCH; kc++) {
            unsigned ca = sa + kc*2 + aHi;
            unsigned a0r[4], a1r[4];
            ldsm4(a0r, aAddr0 + ((ca ^ axr) << 4));
            ldsm4(a1r, aAddr1 + ((ca ^ axr) << 4));
            unsigned cb = sbc + kc*2 + bHi;
            #pragma unroll
            for (int ntp = 0; ntp < NT/2; ntp++) {
                int brow = Cw + ntp*16 + nro;
                unsigned br[4];
                ldsm4(br, Bbase + (unsigned)brow*(ST*16) + ((cb ^ bxr) << 4));
                mma16816(cc[0][ntp*2],   a0r, br[0], br[1]);
                mma16816(cc[0][ntp*2+1], a0r, br[2], br[3]);
                mma16816(cc[1][ntp*2],   a1r, br[0], br[1]);
                mma16816(cc[1][ntp*2+1], a1r, br[2], br[3]);
            }
        }
    }

    // ---- epilogue: bias, Y store, stats, L2 max ----
    float* Y = (LAYER == 0) ? g_y1 : g_y2;
    const int tq = lane >> 2, tr = lane & 3;
    #pragma unroll
    for (int ni = 0; ni < NT; ni++) {
        int cn = Cw + ni*8 + tr*2;
        float b0 = sb[cn], b1 = sb[cn+1];
        float s0=0.f, s1=0.f, q0=0.f, q1=0.f, m0=-3.4e38f, m1=-3.4e38f;
        #pragma unroll
        for (int mi = 0; mi < 2; mi++) {
            float d0 = cc[mi][ni][0] + b0;
            float d1 = cc[mi][ni][1] + b1;
            float d2 = cc[mi][ni][2] + b0;
            float d3 = cc[mi][ni][3] + b1;
            if (LAYER < 2) {
                size_t r = rowBase + Rw + mi*16 + tq;
                *(float2*)&Y[r*64 + cn]     = make_float2(d0, d1);
                *(float2*)&Y[(r+8)*64 + cn] = make_float2(d2, d3);
            }
            s0 += d0 + d2;  s1 += d1 + d3;
            q0 += d0*d0 + d2*d2;  q1 += d1*d1 + d3*d3;
            m0 = fmaxf(m0, fmaxf(d0, d2));  m1 = fmaxf(m1, fmaxf(d1, d3));
        }
        #pragma unroll
        for (int o = 4; o <= 16; o <<= 1) {
            s0 += __shfl_xor_sync(0xffffffffu, s0, o);
            s1 += __shfl_xor_sync(0xffffffffu, s1, o);
            q0 += __shfl_xor_sync(0xffffffffu, q0, o);
            q1 += __shfl_xor_sync(0xffffffffu, q1, o);
            if (LAYER == 2) {
                m0 = fmaxf(m0, __shfl_xor_sync(0xffffffffu, m0, o));
                m1 = fmaxf(m1, __shfl_xor_sync(0xffffffffu, m1, o));
            }
        }
        if (lane < 4) {
            atomicAdd(&ssum[cn],   s0);
            atomicAdd(&ssum[cn+1], s1);
            atomicAdd(&ssq[cn],    q0);
            atomicAdd(&ssq[cn+1],  q1);
            if (LAYER == 2) {
                int bm = (int)(rowBase >> 5) + wm;
                size_t o0 = ((size_t)(bm >> 11)*128 + (unsigned)cn)*2048 + (unsigned)(bm & 2047);
                g_maxf[o0]        = m0;
                g_maxf[o0 + 2048] = m1;
            }
        }
    }
    __syncthreads();
    if (tid < CO) {
        atomicAdd(&g_sum[LAYER][tid], (double)ssum[tid]);
        atomicAdd(&g_sq [LAYER][tid], (double)ssq [tid]);
    }
}

// ---------------- BN stats -> scale/shift (layers 0,1) -------------------
__global__ void finalize_kernel(int L, const float* __restrict__ g,
                                const float* __restrict__ beta, int Co)
{
    int c = threadIdx.x;
    if (c >= Co) return;
    double inv = 1.0 / (double)NROWS;
    double mu  = g_sum[L][c] * inv;
    double var = g_sq[L][c] * inv - mu*mu;
    if (var < 0.0) var = 0.0;
    float s = g[c] / sqrtf((float)var + BN_EPS);
    g_s[L][c] = s;
    g_t[L][c] = fmaf(-(float)mu, s, beta[c]);
}

// ------- BN+ReLU on pre-pooled max (inline finalize for layer 2) ----------
__global__ void maxpool_kernel(float* __restrict__ out,
                               const float* __restrict__ g,
                               const float* __restrict__ beta)
{
    int i = blockIdx.x * blockDim.x + threadIdx.x;   // over B*128*M = 2M
    int c = (i >> 11) & 127;                         // constant per block
    double inv = 1.0 / (double)NROWS;
    double mu  = g_sum[2][c] * inv;
    double var = g_sq[2][c] * inv - mu*mu;
    if (var < 0.0) var = 0.0;
    float s = g[c] / sqrtf((float)var + BN_EPS);
    float t = fmaf(-(float)mu, s, beta[c]);
    out[(size_t)Bb*Mm*3 + i] = fmaxf(fmaf(g_maxf[i], s, t), 0.f);
}

// ---------------- launch ---------------------------------------------------
extern "C" void kernel_launch(void* const* d_in, const int* in_sizes, int n_in,
                              void* d_out, int out_size)
{
    (void)in_sizes; (void)n_in; (void)out_size;
    const float* xyz  = (const float*)d_in[0];
    const float* feats= (const float*)d_in[1];
    const float* W1   = (const float*)d_in[2];
    const float* b1   = (const float*)d_in[3];
    const float* g1   = (const float*)d_in[4];
    const float* be1  = (const float*)d_in[5];
    const float* W2   = (const float*)d_in[6];
    const float* b2   = (const float*)d_in[7];
    const float* g2   = (const float*)d_in[8];
    const float* be2  = (const float*)d_in[9];
    const float* W3   = (const float*)d_in[10];
    const float* b3   = (const float*)d_in[11];
    const float* g3   = (const float*)d_in[12];
    const float* be3  = (const float*)d_in[13];
    float* out = (float*)d_out;
    const float* centers = out;   // knn writes centers into d_out[0 : B*M*3)

    const int SM0 = 128*24*16 + 64*24*16;     // 73728
    const int SM1 = 128*16*16 + 64*16*16;     // 49152
    const int SM2 = 128*16*16 + 128*16*16;    // 65536
    cudaFuncSetAttribute(mma_kernel<0>, cudaFuncAttributeMaxDynamicSharedMemorySize, SM0);
    cudaFuncSetAttribute(mma_kernel<1>, cudaFuncAttributeMaxDynamicSharedMemorySize, SM1);
    cudaFuncSetAttribute(mma_kernel<2>, cudaFuncAttributeMaxDynamicSharedMemorySize, SM2);

    const int KNN_SMEM = 1024*4 + 4*CAPQ*4*2;   // hist + cand arrays = 45056 B

    prep_kernel<<<(Bb*Pp)/256, 256>>>(W1, W2, W3, xyz);
    transpose_kernel<<<dim3(Pp/32, CIN/32, Bb), dim3(32, 8)>>>(feats);
    knn_kernel<<<Bb*512, 256, KNN_SMEM>>>(out);

    mma_kernel<0><<<NROWS/128, 256, SM0>>>(b1, centers);
    finalize_kernel<<<1, 64>>>(0, g1, be1, 64);
    mma_kernel<1><<<NROWS/128, 256, SM1>>>(b2, centers);
    finalize_kernel<<<1, 64>>>(1, g2, be2, 64);
    mma_kernel<2><<<NROWS/128, 256, SM2>>>(b3, centers);

    maxpool_kernel<<<(Bb*Mm*128)/256, 256>>>(out, g3, be3);
}

// round 16
// speedup vs baseline: 1.0911x; 1.0867x over previous
#include <cuda_runtime.h>
#include <cuda_bf16.h>
#include <cstdint>

#define Bb   8
#define Pp   8192
#define CIN  64
#define KK   32
#define Mm   2048
#define NROWS (Bb*Mm*KK)     // 524288
#define BN_EPS 1e-5f

// ---------------- scratch (device globals; no allocation) ----------------
__device__ __align__(128) __nv_bfloat16 g_fh[(size_t)Bb*Pp*CIN]; // feats hi (8 MB)
__device__ __align__(128) __nv_bfloat16 g_fl[(size_t)Bb*Pp*CIN]; // feats lo (8 MB)
__device__ __align__(128) float4 g_xyz4[(size_t)Bb*Pp];          // (x,y,z,|x|^2)
__device__ __align__(128) int    g_sel[(size_t)NROWS];           // 2 MB
__device__ __align__(128) float  g_y1[(size_t)NROWS*64];         // 134 MB
__device__ __align__(128) float  g_y2[(size_t)NROWS*64];         // 134 MB
__device__ __align__(128) float  g_maxf[(size_t)Bb*128*Mm];      // 8 MB
// weight hi/lo bf16 images (unswizzled, K-major rows)
__device__ __align__(128) __nv_bfloat16 g_Wh0[64*80],  g_Wl0[64*80];
__device__ __align__(128) __nv_bfloat16 g_Wh1[64*64],  g_Wl1[64*64];
__device__ __align__(128) __nv_bfloat16 g_Wh2[128*64], g_Wl2[128*64];
__device__ double g_sum[3][128];
__device__ double g_sq[3][128];
__device__ float  g_s[3][128];
__device__ float  g_t[3][128];

// ---------------- small helpers ------------------------------------------
__device__ __forceinline__ uint32_t smem_u32(const void* p) {
    uint32_t a;
    asm("{ .reg .u64 t; cvta.to.shared.u64 t, %1; cvt.u32.u64 %0, t; }" : "=r"(a) : "l"(p));
    return a;
}
__device__ __forceinline__ unsigned pkb(__nv_bfloat16 a, __nv_bfloat16 b) {
    __nv_bfloat162 t; t.x = a; t.y = b;
    return *(unsigned*)&t;
}
__device__ __forceinline__ void wsplit(float w, __nv_bfloat16& h, __nv_bfloat16& l) {
    h = __float2bfloat16(w);
    l = __float2bfloat16(w - __bfloat162float(h));
}
__device__ __forceinline__ unsigned cvt2bf(float hi, float lo) {
    unsigned r;
    asm("cvt.rn.bf16x2.f32 %0, %1, %2;" : "=r"(r) : "f"(hi), "f"(lo));
    return r;
}
__device__ __forceinline__ void ldsm4(unsigned* r, uint32_t addr) {
    asm volatile("ldmatrix.sync.aligned.m8n8.x4.shared.b16 {%0,%1,%2,%3}, [%4];"
        : "=r"(r[0]), "=r"(r[1]), "=r"(r[2]), "=r"(r[3]) : "r"(addr));
}
__device__ __forceinline__ void mma16816(float* c, const unsigned* a,
                                         unsigned b0, unsigned b1) {
    asm volatile("mma.sync.aligned.m16n8k16.row.col.f32.bf16.bf16.f32 "
        "{%0,%1,%2,%3}, {%4,%5,%6,%7}, {%8,%9}, {%0,%1,%2,%3};"
        : "+f"(c[0]), "+f"(c[1]), "+f"(c[2]), "+f"(c[3])
        : "r"(a[0]), "r"(a[1]), "r"(a[2]), "r"(a[3]), "r"(b0), "r"(b1));
}
__device__ __forceinline__ unsigned mapu(float d) {
    unsigned u = __float_as_uint(d);
    return u ^ ((unsigned)(((int)u) >> 31) | 0x80000000u);
}
// packed f32x2 (exact per-lane fp32 rn)
#define PACK2(d, lo, hi)    asm("mov.b64 %0, {%1,%2};" : "=l"(d) : "f"(lo), "f"(hi))
#define UNPACK2F(lo, hi, v) asm("mov.b64 {%0,%1}, %2;" : "=f"(lo), "=f"(hi) : "l"(v))
#define MUL2(d, a, b)       asm("mul.rn.f32x2 %0, %1, %2;" : "=l"(d) : "l"(a), "l"(b))
#define ADD2(d, a, b)       asm("add.rn.f32x2 %0, %1, %2;" : "=l"(d) : "l"(a), "l"(b))

// ------- prep: zero stats + bf16 hi/lo weight images + xyz pad ------------
__global__ void prep_kernel(const float* __restrict__ W1,
                            const float* __restrict__ W2,
                            const float* __restrict__ W3,
                            const float* __restrict__ xyz)
{
    int tid = blockIdx.x * blockDim.x + threadIdx.x;
    if (tid < 384) { ((double*)g_sum)[tid] = 0.0; ((double*)g_sq)[tid] = 0.0; }
    if (tid < 5120 + 4096 + 8192) {
        float w;
        __nv_bfloat16 *ph, *pl;
        int idx;
        if (tid < 5120) {                   // W0: [64][80] = feats(64)+xyz(3)+pad
            int n = tid / 80, k = tid % 80;
            if (k < 64)      w = W1[n*67 + k + 3];
            else if (k < 67) w = W1[n*67 + (k - 64)];
            else             w = 0.f;
            ph = g_Wh0; pl = g_Wl0; idx = tid;
        } else if (tid < 9216) {            // W1: [64][64]
            int t = tid - 5120;
            w = W2[t];
            ph = g_Wh1; pl = g_Wl1; idx = t;
        } else {                            // W2: [128][64]
            int t = tid - 9216;
            w = W3[t];
            ph = g_Wh2; pl = g_Wl2; idx = t;
        }
        __nv_bfloat16 h, l; wsplit(w, h, l);
        ph[idx] = h; pl[idx] = l;
    }
    if (tid < Bb*Pp) {                      // xyz -> float4 (x,y,z,|x|^2)
        const float* s = xyz + (size_t)tid*3;
        float x = s[0], y = s[1], z = s[2];
        float n = __fadd_rn(__fadd_rn(__fmul_rn(x,x), __fmul_rn(y,y)), __fmul_rn(z,z));
        g_xyz4[tid] = make_float4(x, y, z, n);
    }
}

// ---------------- feats (B,C,P) -> bf16 hi/lo (B,P,C) ---------------------
__global__ void transpose_kernel(const float* __restrict__ f)
{
    __shared__ float tile[32][33];
    int b  = blockIdx.z;
    int c0 = blockIdx.y * 32;
    int p0 = blockIdx.x * 32;
    int tx = threadIdx.x, ty = threadIdx.y;
    #pragma unroll
    for (int i = ty; i < 32; i += 8)
        tile[i][tx] = f[((size_t)b*CIN + c0 + i)*Pp + p0 + tx];
    __syncthreads();
    #pragma unroll
    for (int i = ty; i < 32; i += 8) {
        float v = tile[tx][i];
        __nv_bfloat16 h, l; wsplit(v, h, l);
        size_t o = ((size_t)b*Pp + p0 + i)*CIN + c0 + tx;
        g_fh[o] = h;
        g_fl[o] = l;
    }
}

// --- KNN: 4 q/block, exact 4-pass sample pivot, packed sweep, par. tail ---
#define CAPQ 1280
__global__ void __launch_bounds__(256, 4) knn_kernel(float* __restrict__ centers_out)
{
    int blk = blockIdx.x;          // 0..4095
    int b   = blk >> 9;
    int mbase = (blk & 511) * 4;

    extern __shared__ char sm[];
    unsigned* hist    = (unsigned*)sm;                 // 1024 bins (4 x 256)
    unsigned* cand_dm = hist + 1024;                   // 4*CAPQ
    int*      cand_id = (int*)(cand_dm + 4*CAPQ);      // 4*CAPQ
    __shared__ float    ctr[4][4];
    __shared__ float    sTf[4];
    __shared__ unsigned s_prefix[4];
    __shared__ int s_remaining[4], s_ncand[4], s_cnt[4];
    __shared__ int s_min4[4], s_last4[4];
    __shared__ int s_maxrem;

    int tid  = threadIdx.x;
    int wid  = tid >> 5;
    int lane = tid & 31;
    const float4* X4 = g_xyz4 + ((size_t)b << 13);

    if (tid < 4) {
        int m = mbase + tid;
        int ci = (m == 2047) ? 8191
               : (int)(__fmul_rn(8191.0f, __fdiv_rn((float)m, 2047.0f)));
        float4 cp = X4[ci];
        ctr[tid][0] = cp.x; ctr[tid][1] = cp.y; ctr[tid][2] = cp.z; ctr[tid][3] = cp.w;
        float* co = centers_out + (size_t)(b*2048 + m)*3;
        co[0] = cp.x; co[1] = cp.y; co[2] = cp.z;
        s_prefix[tid] = 0u; s_remaining[tid] = KK;
        s_ncand[tid] = 0; s_cnt[tid] = 0; s_last4[tid] = -1;
    }
    __syncthreads();
    float cxq[4], cyq[4], czq[4], cnq[4];
    #pragma unroll
    for (int q = 0; q < 4; q++) {
        cxq[q] = ctr[q][0]; cyq[q] = ctr[q][1]; czq[q] = ctr[q][2]; cnq[q] = ctr[q][3];
    }
    auto distq = [&](int q, float4 X) -> float {
        float dt = __fadd_rn(__fadd_rn(__fmul_rn(cxq[q],X.x), __fmul_rn(cyq[q],X.y)),
                             __fmul_rn(czq[q],X.z));
        return __fsub_rn(__fadd_rn(cnq[q], X.w), __fmul_rn(2.0f, dt));
    };
    auto hadd = [&](bool ok, unsigned bkt) {
        unsigned mask = __ballot_sync(0xffffffffu, ok);
        if (ok) {
            unsigned peers = __match_any_sync(mask, bkt);
            if ((peers & ((1u << lane) - 1u)) == 0u)
                atomicAdd(&hist[bkt], __popc(peers));
        }
    };
    auto scanq = [&](int q, int base) {
        unsigned cum[8];
        unsigned run = 0;
        #pragma unroll
        for (int i = 0; i < 8; i++) { run += hist[base + lane*8 + i]; cum[i] = run; }
        unsigned tot = run;
        unsigned off = tot;
        #pragma unroll
        for (int dd = 1; dd < 32; dd <<= 1) {
            unsigned v = __shfl_up_sync(0xffffffffu, off, dd);
            if (lane >= dd) off += v;
        }
        off -= tot;
        unsigned rem = (unsigned)s_remaining[q];
        #pragma unroll
        for (int i = 0; i < 8; i++) {
            unsigned prev = off + (i ? cum[i-1] : 0u);
            unsigned cu   = off + cum[i];
            if (prev < rem && cu >= rem) {
                s_prefix[q] = (s_prefix[q] << 8) | (unsigned)(lane*8 + i);
                s_remaining[q] = (int)(rem - prev);
            }
        }
    };

    // ---- sample phase: 512 points {16t,16t+1}; exact 4-pass pivot ----
    unsigned sd[4][2];
    {
        float4 A = __ldg(X4 + 16*tid);
        float4 Bp = __ldg(X4 + 16*tid + 1);
        #pragma unroll
        for (int q = 0; q < 4; q++) {
            sd[q][0] = mapu(distq(q, A));
            sd[q][1] = mapu(distq(q, Bp));
        }
    }
    for (int pass = 0; pass < 4; pass++) {
        #pragma unroll
        for (int t = tid; t < 1024; t += 256) hist[t] = 0;
        __syncthreads();
        unsigned prefq[4];
        #pragma unroll
        for (int q = 0; q < 4; q++) prefq[q] = s_prefix[q];
        int sh = 24 - 8*pass;
        #pragma unroll
        for (int q = 0; q < 4; q++) {
            #pragma unroll
            for (int k = 0; k < 2; k++) {
                bool ok = (pass == 0) || ((sd[q][k] >> (sh + 8)) == prefq[q]);
                hadd(ok, (unsigned)(q*256) + ((sd[q][k] >> sh) & 255u));
            }
        }
        __syncthreads();
        if (wid < 4) scanq(wid, wid*256);
        __syncthreads();
    }
    if (tid < 4) {
        unsigned mv = s_prefix[tid];
        unsigned u  = (mv & 0x80000000u) ? (mv ^ 0x80000000u) : ~mv;
        sTf[tid] = __uint_as_float(u);
        s_prefix[tid] = 0u; s_remaining[tid] = KK;
    }
    __syncthreads();
    float Tf[4] = {sTf[0], sTf[1], sTf[2], sTf[3]};

    // packed query constants: {q0,q1} and {q2,q3}
    unsigned long long qx01, qx23, qy01, qy23, qz01, qz23, qn01, qn23;
    PACK2(qx01, cxq[0], cxq[1]); PACK2(qx23, cxq[2], cxq[3]);
    PACK2(qy01, cyq[0], cyq[1]); PACK2(qy23, cyq[2], cyq[3]);
    PACK2(qz01, czq[0], czq[1]); PACK2(qz23, czq[2], czq[3]);
    PACK2(qn01, cnq[0], cnq[1]); PACK2(qn23, cnq[2], cnq[3]);

    // ---- main sweep: 1 LDG.128/point, packed f32x2 exact distances ----
    #pragma unroll 4
    for (int jj = 0; jj < 32; jj++) {
        int p = tid + jj*256;
        float4 X = __ldg(X4 + p);
        unsigned long long Xx, Xy, Xz, Xw;
        PACK2(Xx, X.x, X.x); PACK2(Xy, X.y, X.y);
        PACK2(Xz, X.z, X.z); PACK2(Xw, X.w, X.w);
        unsigned long long t, u, d01, d23;
        MUL2(t, qx01, Xx); MUL2(u, qy01, Xy); ADD2(t, t, u);
        MUL2(u, qz01, Xz); ADD2(t, t, u);
        ADD2(t, t, t); t ^= 0x8000000080000000ULL;
        ADD2(u, qn01, Xw); ADD2(d01, u, t);
        MUL2(t, qx23, Xx); MUL2(u, qy23, Xy); ADD2(t, t, u);
        MUL2(u, qz23, Xz); ADD2(t, t, u);
        ADD2(t, t, t); t ^= 0x8000000080000000ULL;
        ADD2(u, qn23, Xw); ADD2(d23, u, t);
        float d0, d1, d2, d3;
        UNPACK2F(d0, d1, d01);
        UNPACK2F(d2, d3, d23);
        if (d0 <= Tf[0]) {
            int pos = atomicAdd(&s_ncand[0], 1);
            if (pos < CAPQ) { cand_dm[0*CAPQ + pos] = mapu(d0); cand_id[0*CAPQ + pos] = p; }
        }
        if (d1 <= Tf[1]) {
            int pos = atomicAdd(&s_ncand[1], 1);
            if (pos < CAPQ) { cand_dm[1*CAPQ + pos] = mapu(d1); cand_id[1*CAPQ + pos] = p; }
        }
        if (d2 <= Tf[2]) {
            int pos = atomicAdd(&s_ncand[2], 1);
            if (pos < CAPQ) { cand_dm[2*CAPQ + pos] = mapu(d2); cand_id[2*CAPQ + pos] = p; }
        }
        if (d3 <= Tf[3]) {
            int pos = atomicAdd(&s_ncand[3], 1);
            if (pos < CAPQ) { cand_dm[3*CAPQ + pos] = mapu(d3); cand_id[3*CAPQ + pos] = p; }
        }
    }
    __syncthreads();

    int nc[4];
    bool anyofl = false;
    #pragma unroll
    for (int q = 0; q < 4; q++) { nc[q] = s_ncand[q]; anyofl |= (nc[q] > CAPQ); }

    // ---- candidate radix: 4 queries in PARALLEL (exact cand_dm stored) ----
    for (int pass = 0; pass < 4; pass++) {
        #pragma unroll
        for (int t = tid; t < 1024; t += 256) hist[t] = 0;
        __syncthreads();
        int sh = 24 - 8*pass;
        #pragma unroll
        for (int q = 0; q < 4; q++) {
            if (nc[q] > CAPQ) continue;
            unsigned pref = s_prefix[q];
            for (int it = 0; it*256 < nc[q]; it++) {
                int t = it*256 + tid;
                unsigned dv = (t < nc[q]) ? cand_dm[q*CAPQ + t] : 0u;
                bool ok = (t < nc[q]) && ((pass == 0) || ((dv >> (sh + 8)) == pref));
                hadd(ok, (unsigned)(q*256) + ((dv >> sh) & 255u));
            }
        }
        __syncthreads();
        if (wid < 4 && nc[wid] <= CAPQ) scanq(wid, wid*256);
        __syncthreads();
    }

    // ---- selection: 4 queries in parallel ----
    #pragma unroll
    for (int q = 0; q < 4; q++) {
        if (nc[q] > CAPQ) continue;
        unsigned thr = s_prefix[q];
        int* selg = g_sel + (size_t)(b*2048 + mbase + q) * KK;
        for (int it = 0; it*256 < nc[q]; it++) {
            int t = it*256 + tid;
            if (t < nc[q] && cand_dm[q*CAPQ + t] < thr) {
                int s = atomicAdd(&s_cnt[q], 1);
                selg[s] = cand_id[q*CAPQ + t];
            }
        }
    }
    __syncthreads();
    if (tid == 0) {
        int mr = 0;
        for (int q = 0; q < 4; q++)
            if (nc[q] <= CAPQ && s_remaining[q] > mr) mr = s_remaining[q];
        s_maxrem = mr;
    }
    __syncthreads();
    int maxrem = s_maxrem;
    for (int r = 0; r < maxrem; r++) {
        if (tid < 4) s_min4[tid] = 0x7fffffff;
        __syncthreads();
        #pragma unroll
        for (int q = 0; q < 4; q++) {
            if (nc[q] > CAPQ || r >= s_remaining[q]) continue;
            unsigned thr = s_prefix[q];
            int last = s_last4[q];
            for (int it = 0; it*256 < nc[q]; it++) {
                int t = it*256 + tid;
                if (t < nc[q] && cand_dm[q*CAPQ + t] == thr && cand_id[q*CAPQ + t] > last)
                    atomicMin(&s_min4[q], cand_id[q*CAPQ + t]);
            }
        }
        __syncthreads();
        if (tid < 4) {
            int q = tid;
            if (nc[q] <= CAPQ && r < s_remaining[q]) {
                int* selg = g_sel + (size_t)(b*2048 + mbase + q) * KK;
                selg[s_cnt[q] + r] = s_min4[q];
                s_last4[q] = s_min4[q];
            }
        }
        __syncthreads();
    }

    // ---- exact fallback for overflow queries (rare) ----
    if (anyofl) {
        for (int q = 0; q < 4; q++) {
            if (nc[q] <= CAPQ) continue;
            __syncthreads();
            if (tid == 0) { s_prefix[q] = 0u; s_remaining[q] = KK; s_cnt[q] = 0; s_last4[q] = -1; }
            __syncthreads();
            for (int pass = 0; pass < 4; pass++) {
                hist[tid] = 0;
                __syncthreads();
                unsigned pref = s_prefix[q];
                int sh = 24 - 8*pass;
                for (int jj = 0; jj < 32; jj++) {
                    float4 X = __ldg(X4 + tid + jj*256);
                    unsigned u = mapu(distq(q, X));
                    bool ok = (pass == 0) || ((u >> (sh + 8)) == pref);
                    hadd(ok, (u >> sh) & 255u);
                }
                __syncthreads();
                if (wid == 0) scanq(q, 0);
                __syncthreads();
            }
            unsigned thr = s_prefix[q];
            int rem = s_remaining[q];
            int* selg = g_sel + (size_t)(b*2048 + mbase + q) * KK;
            for (int jj = 0; jj < 32; jj++) {
                int p = tid + jj*256;
                float4 X = __ldg(X4 + p);
                if (mapu(distq(q, X)) < thr) {
                    int s = atomicAdd(&s_cnt[q], 1);
                    selg[s] = p;
                }
            }
            __syncthreads();
            int base = s_cnt[q];
            for (int r = 0; r < rem; r++) {
                if (tid == 0) s_min4[0] = 0x7fffffff;
                __syncthreads();
                int last = s_last4[q];
                for (int jj = 0; jj < 32; jj++) {
                    int p = tid + jj*256;
                    float4 X = __ldg(X4 + p);
                    if (mapu(distq(q, X)) == thr && p > last) atomicMin(&s_min4[0], p);
                }
                __syncthreads();
                if (tid == 0) { selg[base + r] = s_min4[0]; s_last4[q] = s_min4[0]; }
                __syncthreads();
            }
        }
    }
}

// ---------------- bf16x3 GEMM via mma.sync (fused-segment loop) -----------
template<int LAYER>
__global__ void __launch_bounds__(256) mma_kernel(const float* __restrict__ bias,
                                                  const float* __restrict__ centers)
{
    constexpr int CO    = (LAYER == 2) ? 128 : 64;
    constexpr int K     = (LAYER == 0) ? 80 : 64;
    constexpr int KC    = K / 8;
    constexpr int NKCH  = K / 16;
    constexpr int ST    = (LAYER == 0) ? 24 : 16;
    constexpr int ASZ   = 128 * ST * 16;
    constexpr int WCOLS = CO / 2;
    constexpr int NT    = WCOLS / 8;
    constexpr int HC    = KC / 2;

    extern __shared__ __align__(16) char dyn[];
    char* Asm = dyn;
    char* Bsm = dyn + ASZ;
    __shared__ float sb[CO], ssum[CO], ssq[CO];
    __shared__ float sS[64], sT[64];

    const int tid = threadIdx.x;
    const size_t rowBase = (size_t)blockIdx.x * 128;
    const int bBat = (int)(rowBase >> 16);

    if (tid < CO) { sb[tid] = bias[tid]; ssum[tid] = 0.f; ssq[tid] = 0.f; }
    if (LAYER > 0 && tid < 64) { sS[tid] = g_s[LAYER-1][tid]; sT[tid] = g_t[LAYER-1][tid]; }
    __syncthreads();

    // ---- A build: 2 threads per row ----
    {
        int row = tid >> 1, half = tid & 1;
        int rx = row & 7;
        unsigned rowOff = (unsigned)row * (ST*16);
        if (LAYER == 0) {
            int p = g_sel[rowBase + row];
            const uint4* FH = (const uint4*)g_fh + (((size_t)bBat << 13) + (unsigned)p) * 8;
            const uint4* FL = (const uint4*)g_fl + (((size_t)bBat << 13) + (unsigned)p) * 8;
            #pragma unroll
            for (int j = 0; j < HC; j++) {
                int c = half*HC + j;
                uint4 hv4, lv4;
                if (c < 8) {
                    hv4 = __ldg(FH + c);
                    lv4 = __ldg(FL + c);
                } else if (c == 8) {
                    float4 X = g_xyz4[((size_t)bBat << 13) + (unsigned)p];
                    int bm = (int)((rowBase + row) >> 5);
                    float dx = X.x - centers[bm*3 + 0];
                    float dy = X.y - centers[bm*3 + 1];
                    float dz = X.z - centers[bm*3 + 2];
                    unsigned h01 = cvt2bf(dy, dx);
                    float h0f = __uint_as_float(h01 << 16);
                    float h1f = __uint_as_float(h01 & 0xffff0000u);
                    unsigned l01 = cvt2bf(dy - h1f, dx - h0f);
                    unsigned h2 = cvt2bf(0.f, dz);
                    float h2f = __uint_as_float(h2 << 16);
                    unsigned l2 = cvt2bf(0.f, dz - h2f);
                    hv4 = make_uint4(h01, h2, 0u, 0u);
                    lv4 = make_uint4(l01, l2, 0u, 0u);
                } else {
                    hv4 = make_uint4(0u, 0u, 0u, 0u);
                    lv4 = make_uint4(0u, 0u, 0u, 0u);
                }
                unsigned ch = (unsigned)(c ^ rx);
                unsigned cl = (unsigned)((KC + c) ^ rx);
                *(uint4*)(Asm + rowOff + ch*16) = hv4;
                *(uint4*)(Asm + rowOff + cl*16) = lv4;
            }
        } else {
            const float* srcf = ((LAYER == 1) ? g_y1 : g_y2) + (rowBase + row) * 64;
            #pragma unroll
            for (int j = 0; j < HC; j++) {
                int c  = half*HC + j;
                int k0 = c*8;
                float4 v0 = *(const float4*)(srcf + k0);
                float4 v1 = *(const float4*)(srcf + k0 + 4);
                float f[8] = {v0.x,v0.y,v0.z,v0.w,v1.x,v1.y,v1.z,v1.w};
                #pragma unroll
                for (int i = 0; i < 8; i++)
                    f[i] = fmaxf(fmaf(f[i], sS[k0+i], sT[k0+i]), 0.f);
                unsigned hv[4], lv[4];
                #pragma unroll
                for (int q = 0; q < 4; q++) {
                    float f0 = f[2*q], f1 = f[2*q+1];
                    unsigned h = cvt2bf(f1, f0);
                    float h0f = __uint_as_float(h << 16);
                    float h1f = __uint_as_float(h & 0xffff0000u);
                    hv[q] = h;
                    lv[q] = cvt2bf(f1 - h1f, f0 - h0f);
                }
                unsigned ch = (unsigned)(c ^ rx);
                unsigned cl = (unsigned)((KC + c) ^ rx);
                *(uint4*)(Asm + rowOff + ch*16) = make_uint4(hv[0],hv[1],hv[2],hv[3]);
                *(uint4*)(Asm + rowOff + cl*16) = make_uint4(lv[0],lv[1],lv[2],lv[3]);
            }
        }
    }
    // ---- B copy: hi/lo images -> swizzled smem ----
    {
        const __nv_bfloat16* Wh = (LAYER==0) ? g_Wh0 : (LAYER==1) ? g_Wh1 : g_Wh2;
        const __nv_bfloat16* Wl = (LAYER==0) ? g_Wl0 : (LAYER==1) ? g_Wl1 : g_Wl2;
        for (int i = tid; i < CO * 2 * KC; i += 256) {
            int n = i / (2*KC), c = i % (2*KC);
            const __nv_bfloat16* src = (c < KC) ? (Wh + n*K + c*8)
                                                : (Wl + n*K + (c - KC)*8);
            uint4 v = *(const uint4*)src;
            unsigned cs = (unsigned)(c ^ (n & 7));
            *(uint4*)(Bsm + (unsigned)n*(ST*16) + cs*16) = v;
        }
    }
    __syncthreads();

    // ---- MMA main loop: fused segments (aH,aL,bH,bL loaded once per kc) ----
    const uint32_t Abase = smem_u32(Asm);
    const uint32_t Bbase = smem_u32(Bsm);
    const int warp = tid >> 5, lane = tid & 31;
    const int wm = warp >> 1, wn = warp & 1;
    const int Rw = wm*32, Cw = wn*WCOLS;

    const int arow = lane & 15;
    const uint32_t aAddr0 = Abase + (unsigned)(Rw + arow)      * (ST*16);
    const uint32_t aAddr1 = Abase + (unsigned)(Rw + 16 + arow) * (ST*16);
    const unsigned axr = (unsigned)(arow & 7);
    const unsigned aHi = (unsigned)(lane >> 4);
    const int nro  = (lane & 7) + ((lane & 16) >> 1);
    const unsigned bxr = (unsigned)(nro & 7);
    const unsigned bHi = (unsigned)((lane >> 3) & 1);

    float cc[2][NT][4];
    #pragma unroll
    for (int mi = 0; mi < 2; mi++)
        #pragma unroll
        for (int ni = 0; ni < NT; ni++)
            #pragma unroll
            for (int q = 0; q < 4; q++) cc[mi][ni][q] = 0.f;

    #pragma unroll
    for (int kc = 0; kc < NKCH; kc++) {
        unsigned caH = kc*2 + aHi;
        unsigned caL = KC + kc*2 + aHi;
        unsigned aH0[4], aH1[4], aL0[4], aL1[4];
        ldsm4(aH0, aAddr0 + ((caH ^ axr) << 4));
        ldsm4(aH1, aAddr1 + ((caH ^ axr) << 4));
        ldsm4(aL0, aAddr0 + ((caL ^ axr) << 4));
        ldsm4(aL1, aAddr1 + ((caL ^ axr) << 4));
        unsigned cbH = kc*2 + bHi;
        unsigned cbL = KC + kc*2 + bHi;
        #pragma unroll
        for (int ntp = 0; ntp < NT/2; ntp++) {
            int brow = Cw + ntp*16 + nro;
            uint32_t bAddr = Bbase + (unsigned)brow*(ST*16);
            unsigned bh[4], bl[4];
            ldsm4(bh, bAddr + ((cbH ^ bxr) << 4));
            ldsm4(bl, bAddr + ((cbL ^ bxr) << 4));
            // term 1: aH * bH
            mma16816(cc[0][ntp*2],   aH0, bh[0], bh[1]);
            mma16816(cc[0][ntp*2+1], aH0, bh[2], bh[3]);
            mma16816(cc[1][ntp*2],   aH1, bh[0], bh[1]);
            mma16816(cc[1][ntp*2+1], aH1, bh[2], bh[3]);
            // term 2: aL * bH
            mma16816(cc[0][ntp*2],   aL0, bh[0], bh[1]);
            mma16816(cc[0][ntp*2+1], aL0, bh[2], bh[3]);
            mma16816(cc[1][ntp*2],   aL1, bh[0], bh[1]);
            mma16816(cc[1][ntp*2+1], aL1, bh[2], bh[3]);
            // term 3: aH * bL
            mma16816(cc[0][ntp*2],   aH0, bl[0], bl[1]);
            mma16816(cc[0][ntp*2+1], aH0, bl[2], bl[3]);
            mma16816(cc[1][ntp*2],   aH1, bl[0], bl[1]);
            mma16816(cc[1][ntp*2+1], aH1, bl[2], bl[3]);
        }
    }

    // ---- epilogue: bias, Y store, stats, L2 max ----
    float* Y = (LAYER == 0) ? g_y1 : g_y2;
    const int tq = lane >> 2, tr = lane & 3;
    #pragma unroll
    for (int ni = 0; ni < NT; ni++) {
        int cn = Cw + ni*8 + tr*2;
        float b0 = sb[cn], b1 = sb[cn+1];
        float s0=0.f, s1=0.f, q0=0.f, q1=0.f, m0=-3.4e38f, m1=-3.4e38f;
        #pragma unroll
        for (int mi = 0; mi < 2; mi++) {
            float d0 = cc[mi][ni][0] + b0;
            float d1 = cc[mi][ni][1] + b1;
            float d2 = cc[mi][ni][2] + b0;
            float d3 = cc[mi][ni][3] + b1;
            if (LAYER < 2) {
                size_t r = rowBase + Rw + mi*16 + tq;
                *(float2*)&Y[r*64 + cn]     = make_float2(d0, d1);
                *(float2*)&Y[(r+8)*64 + cn] = make_float2(d2, d3);
            }
            s0 += d0 + d2;  s1 += d1 + d3;
            q0 += d0*d0 + d2*d2;  q1 += d1*d1 + d3*d3;
            m0 = fmaxf(m0, fmaxf(d0, d2));  m1 = fmaxf(m1, fmaxf(d1, d3));
        }
        #pragma unroll
        for (int o = 4; o <= 16; o <<= 1) {
            s0 += __shfl_xor_sync(0xffffffffu, s0, o);
            s1 += __shfl_xor_sync(0xffffffffu, s1, o);
            q0 += __shfl_xor_sync(0xffffffffu, q0, o);
            q1 += __shfl_xor_sync(0xffffffffu, q1, o);
            if (LAYER == 2) {
                m0 = fmaxf(m0, __shfl_xor_sync(0xffffffffu, m0, o));
                m1 = fmaxf(m1, __shfl_xor_sync(0xffffffffu, m1, o));
            }
        }
        if (lane < 4) {
            atomicAdd(&ssum[cn],   s0);
            atomicAdd(&ssum[cn+1], s1);
            atomicAdd(&ssq[cn],    q0);
            atomicAdd(&ssq[cn+1],  q1);
            if (LAYER == 2) {
                int bm = (int)(rowBase >> 5) + wm;
                size_t o0 = ((size_t)(bm >> 11)*128 + (unsigned)cn)*2048 + (unsigned)(bm & 2047);
                g_maxf[o0]        = m0;
                g_maxf[o0 + 2048] = m1;
            }
        }
    }
    __syncthreads();
    if (tid < CO) {
        atomicAdd(&g_sum[LAYER][tid], (double)ssum[tid]);
        atomicAdd(&g_sq [LAYER][tid], (double)ssq [tid]);
    }
}

// ---------------- BN stats -> scale/shift (layers 0,1) -------------------
__global__ void finalize_kernel(int L, const float* __restrict__ g,
                                const float* __restrict__ beta, int Co)
{
    int c = threadIdx.x;
    if (c >= Co) return;
    double inv = 1.0 / (double)NROWS;
    double mu  = g_sum[L][c] * inv;
    double var = g_sq[L][c] * inv - mu*mu;
    if (var < 0.0) var = 0.0;
    float s = g[c] / sqrtf((float)var + BN_EPS);
    g_s[L][c] = s;
    g_t[L][c] = fmaf(-(float)mu, s, beta[c]);
}

// ------- BN+ReLU on pre-pooled max (inline finalize for layer 2) ----------
__global__ void maxpool_kernel(float* __restrict__ out,
                               const float* __restrict__ g,
                               const float* __restrict__ beta)
{
    int i = blockIdx.x * blockDim.x + threadIdx.x;   // over B*128*M = 2M
    int c = (i >> 11) & 127;                         // constant per block
    double inv = 1.0 / (double)NROWS;
    double mu  = g_sum[2][c] * inv;
    double var = g_sq[2][c] * inv - mu*mu;
    if (var < 0.0) var = 0.0;
    float s = g[c] / sqrtf((float)var + BN_EPS);
    float t = fmaf(-(float)mu, s, beta[c]);
    out[(size_t)Bb*Mm*3 + i] = fmaxf(fmaf(g_maxf[i], s, t), 0.f);
}

// ---------------- launch ---------------------------------------------------
extern "C" void kernel_launch(void* const* d_in, const int* in_sizes, int n_in,
                              void* d_out, int out_size)
{
    (void)in_sizes; (void)n_in; (void)out_size;
    const float* xyz  = (const float*)d_in[0];
    const float* feats= (const float*)d_in[1];
    const float* W1   = (const float*)d_in[2];
    const float* b1   = (const float*)d_in[3];
    const float* g1   = (const float*)d_in[4];
    const float* be1  = (const float*)d_in[5];
    const float* W2   = (const float*)d_in[6];
    const float* b2   = (const float*)d_in[7];
    const float* g2   = (const float*)d_in[8];
    const float* be2  = (const float*)d_in[9];
    const float* W3   = (const float*)d_in[10];
    const float* b3   = (const float*)d_in[11];
    const float* g3   = (const float*)d_in[12];
    const float* be3  = (const float*)d_in[13];
    float* out = (float*)d_out;
    const float* centers = out;   // knn writes centers into d_out[0 : B*M*3)

    const int SM0 = 128*24*16 + 64*24*16;     // 73728
    const int SM1 = 128*16*16 + 64*16*16;     // 49152
    const int SM2 = 128*16*16 + 128*16*16;    // 65536
    cudaFuncSetAttribute(mma_kernel<0>, cudaFuncAttributeMaxDynamicSharedMemorySize, SM0);
    cudaFuncSetAttribute(mma_kernel<1>, cudaFuncAttributeMaxDynamicSharedMemorySize, SM1);
    cudaFuncSetAttribute(mma_kernel<2>, cudaFuncAttributeMaxDynamicSharedMemorySize, SM2);

    const int KNN_SMEM = 1024*4 + 4*CAPQ*4*2;   // hist + cand arrays = 45056 B

    prep_kernel<<<(Bb*Pp)/256, 256>>>(W1, W2, W3, xyz);
    transpose_kernel<<<dim3(Pp/32, CIN/32, Bb), dim3(32, 8)>>>(feats);
    knn_kernel<<<Bb*512, 256, KNN_SMEM>>>(out);

    mma_kernel<0><<<NROWS/128, 256, SM0>>>(b1, centers);
    finalize_kernel<<<1, 64>>>(0, g1, be1, 64);
    mma_kernel<1><<<NROWS/128, 256, SM1>>>(b2, centers);
    finalize_kernel<<<1, 64>>>(1, g2, be2, 64);
    mma_kernel<2><<<NROWS/128, 256, SM2>>>(b3, centers);

    maxpool_kernel<<<(Bb*Mm*128)/256, 256>>>(out, g3, be3);
}